// round 3
// baseline (speedup 1.0000x reference)
#include <cuda_runtime.h>
#include <cstdint>
#include <cstddef>

#define BATCH 4
#define SEQ   1024
#define DMODEL 1024
#define NH    16
#define HD    64

// ---------------- scratch (device globals: no runtime allocation) ----------
__device__ float g_xn[BATCH*SEQ*DMODEL];     // layernormed input, tf32-rounded
__device__ float g_wt[3*DMODEL*DMODEL];      // [Wq|Wk|Wv], tf32-rounded
__device__ float g_q[BATCH*SEQ*DMODEL];      // (B,H,S,64), tf32-rounded
__device__ float g_k[BATCH*SEQ*DMODEL];
__device__ float g_v[BATCH*SEQ*DMODEL];
__device__ float g_rinv[BATCH*NH*SEQ];       // 1/rowsum per (b,h,q)

// round-to-nearest tf32 (kills truncation bias; keeps rel err ~2e-4)
__device__ __forceinline__ float tf32r(float f){
    unsigned u; asm("cvt.rna.tf32.f32 %0, %1;" : "=r"(u) : "f"(f));
    return __uint_as_float(u);
}

__device__ __forceinline__ void cpa16(void* dst, const void* src){
    unsigned d = (unsigned)__cvta_generic_to_shared(dst);
    asm volatile("cp.async.cg.shared.global [%0], [%1], 16;" :: "r"(d), "l"(src));
}
__device__ __forceinline__ void cp_commit(){ asm volatile("cp.async.commit_group;"); }
__device__ __forceinline__ void cp_wait0(){ asm volatile("cp.async.wait_group 0;"); }
__device__ __forceinline__ void cp_wait1(){ asm volatile("cp.async.wait_group 1;"); }

#define MMA_TF32(d, a, b_) \
  asm volatile("mma.sync.aligned.m16n8k8.row.col.f32.tf32.tf32.f32 " \
    "{%0,%1,%2,%3},{%4,%5,%6,%7},{%8,%9},{%0,%1,%2,%3};" \
    : "+f"((d)[0]),"+f"((d)[1]),"+f"((d)[2]),"+f"((d)[3]) \
    : "r"((a)[0]),"r"((a)[1]),"r"((a)[2]),"r"((a)[3]),"r"((b_)[0]),"r"((b_)[1]))

// ---------------- Kernel 0: pre-round W to tf32 ----------------------------
__global__ void __launch_bounds__(256) prep_w(const float* __restrict__ Wq,
    const float* __restrict__ Wk, const float* __restrict__ Wv)
{
    int i = blockIdx.x * 256 + threadIdx.x;          // float4 index, 786432 total
    const float* src = (i < 262144) ? Wq : (i < 524288) ? Wk : Wv;
    float4 v = ((const float4*)src)[i & 0x3FFFF];
    v.x = tf32r(v.x); v.y = tf32r(v.y); v.z = tf32r(v.z); v.w = tf32r(v.w);
    ((float4*)g_wt)[i] = v;
}

// ---------------- Kernel 1: LayerNorm (fp32 stats, tf32-rounded output) ----
__global__ void __launch_bounds__(256) ln_kernel(const float* __restrict__ x,
    const float* __restrict__ gamma, const float* __restrict__ beta)
{
    int row = blockIdx.x;
    int tid = threadIdx.x, lane = tid & 31, wid = tid >> 5;
    const float4* xr = (const float4*)(x + (size_t)row * DMODEL);
    float4 v = xr[tid];
    float s  = v.x + v.y + v.z + v.w;
    float sq = v.x*v.x + v.y*v.y + v.z*v.z + v.w*v.w;
    #pragma unroll
    for (int o = 16; o > 0; o >>= 1){
        s  += __shfl_xor_sync(0xffffffffu, s,  o);
        sq += __shfl_xor_sync(0xffffffffu, sq, o);
    }
    __shared__ float ws[8], wq[8], stat[2];
    if (lane == 0){ ws[wid] = s; wq[wid] = sq; }
    __syncthreads();
    if (wid == 0){
        float a = (lane < 8) ? ws[lane] : 0.f;
        float q = (lane < 8) ? wq[lane] : 0.f;
        #pragma unroll
        for (int o = 4; o > 0; o >>= 1){
            a += __shfl_xor_sync(0xffffffffu, a, o);
            q += __shfl_xor_sync(0xffffffffu, q, o);
        }
        if (lane == 0){
            float mean = a * (1.0f / DMODEL);
            float var  = q * (1.0f / DMODEL) - mean * mean;
            stat[0] = mean; stat[1] = rsqrtf(var + 1e-5f);
        }
    }
    __syncthreads();
    float mean = stat[0], rstd = stat[1];
    float4 g  = ((const float4*)gamma)[tid];
    float4 be = ((const float4*)beta)[tid];
    float4 y;
    y.x = tf32r((v.x - mean) * rstd * g.x + be.x);
    y.y = tf32r((v.y - mean) * rstd * g.y + be.y);
    y.z = tf32r((v.z - mean) * rstd * g.z + be.z);
    y.w = tf32r((v.w - mean) * rstd * g.w + be.w);
    ((float4*)(g_xn + (size_t)row * DMODEL))[tid] = y;
}

// ---------------- Kernel 2: QKV projection GEMM (tf32 mma, cp.async x2) ----
#define PA_LD 36
#define PB_LD 136
__global__ void __launch_bounds__(256,2) proj_kernel(
    const float* __restrict__ bq, const float* __restrict__ bk,
    const float* __restrict__ bv)
{
    __shared__ float As[2][128*PA_LD];
    __shared__ float Bs[2][32*PB_LD];

    int m0 = blockIdx.x * 128;
    int by = blockIdx.y;
    int wsel = by >> 3;
    int n0 = (by & 7) * 128;
    const float* W    = g_wt + (size_t)wsel * DMODEL * DMODEL;
    const float* bias = (wsel == 0) ? bq : (wsel == 1) ? bk : bv;
    float* out        = (wsel == 0) ? g_q : (wsel == 1) ? g_k : g_v;

    int tid = threadIdx.x, lane = tid & 31, wid = tid >> 5;
    int gid = lane >> 2, tig = lane & 3;
    int wr = wid >> 2, wc = wid & 3;     // warp tile: 64 rows x 32 cols

    float acc[4][4][4];
    #pragma unroll
    for (int i=0;i<4;i++)
      #pragma unroll
      for (int j=0;j<4;j++)
        #pragma unroll
        for (int r=0;r<4;r++) acc[i][j][r] = 0.f;

    // stage loader: A 128x32, B 32x128
    auto load_stage = [&](int buf, int k0){
        #pragma unroll
        for (int s = 0; s < 4; s++){
            int idx = tid + 256*s;
            int r = idx >> 3, c4 = idx & 7;
            cpa16(&As[buf][r*PA_LD + c4*4],
                  g_xn + (size_t)(m0 + r)*1024 + k0 + c4*4);
        }
        #pragma unroll
        for (int s = 0; s < 4; s++){
            int idx = tid + 256*s;
            int r = idx >> 5, c4 = idx & 31;
            cpa16(&Bs[buf][r*PB_LD + c4*4],
                  W + (size_t)(k0 + r)*1024 + n0 + c4*4);
        }
    };

    load_stage(0, 0);
    cp_commit();

    for (int it = 0; it < 32; it++){
        int buf = it & 1;
        if (it < 31){ load_stage(buf^1, (it+1)*32); cp_commit(); cp_wait1(); }
        else cp_wait0();
        __syncthreads();
        #pragma unroll
        for (int ks = 0; ks < 32; ks += 8){
            unsigned a[4][4], bfr[4][2];
            #pragma unroll
            for (int i=0;i<4;i++){
                int m = wr*64 + i*16 + gid;
                a[i][0] = __float_as_uint(As[buf][m*PA_LD     + ks + tig]);
                a[i][1] = __float_as_uint(As[buf][(m+8)*PA_LD + ks + tig]);
                a[i][2] = __float_as_uint(As[buf][m*PA_LD     + ks + tig + 4]);
                a[i][3] = __float_as_uint(As[buf][(m+8)*PA_LD + ks + tig + 4]);
            }
            #pragma unroll
            for (int j=0;j<4;j++){
                int n = wc*32 + j*8 + gid;
                bfr[j][0] = __float_as_uint(Bs[buf][(ks+tig)*PB_LD   + n]);
                bfr[j][1] = __float_as_uint(Bs[buf][(ks+tig+4)*PB_LD + n]);
            }
            #pragma unroll
            for (int i=0;i<4;i++)
                #pragma unroll
                for (int j=0;j<4;j++)
                    MMA_TF32(acc[i][j], a[i], bfr[j]);
        }
        __syncthreads();
    }
    // epilogue: bias + tf32 round + scatter to (B,H,S,64)
    #pragma unroll
    for (int i=0;i<4;i++){
        int m  = m0 + wr*64 + i*16 + gid;
        int bb = m >> 10, s1 = m & 1023;
        #pragma unroll
        for (int j=0;j<4;j++){
            int nl = n0 + wc*32 + j*8 + 2*tig;
            int h = nl >> 6, d = nl & 63;
            size_t base = ((size_t)(bb*NH + h)*SEQ + s1)*HD + d;
            float2 v0 = make_float2(tf32r(acc[i][j][0] + bias[nl]),
                                    tf32r(acc[i][j][1] + bias[nl+1]));
            *(float2*)(out + base) = v0;
            float2 v1 = make_float2(tf32r(acc[i][j][2] + bias[nl]),
                                    tf32r(acc[i][j][3] + bias[nl+1]));
            *(float2*)(out + base + (size_t)8*HD) = v1;
        }
    }
}

// ---------------- Kernel 3: single-pass attention ---------------------------
#define KS_LD 68
#define VS_LD 72
#define PS_LD 132
#define ATTN_SMEM_FLOATS (2*128*KS_LD + 2*128*VS_LD + 128*PS_LD + 256)
#define ATTN_SMEM_BYTES  (ATTN_SMEM_FLOATS*4)

__global__ void __launch_bounds__(256) attn_kernel(
    const float* __restrict__ x, const int* __restrict__ kvlen,
    float* __restrict__ seq, float* __restrict__ attn_out)
{
    extern __shared__ float sm[];
    float* Ks0  = sm;
    float* Ks1  = Ks0 + 128*KS_LD;
    float* Vs0  = Ks1 + 128*KS_LD;
    float* Vs1  = Vs0 + 128*VS_LD;
    float* Ps   = Vs1 + 128*VS_LD;
    float* rsum = Ps  + 128*PS_LD;
    float* rinv = rsum + 128;
    float* Kbuf[2] = {Ks0, Ks1};
    float* Vbuf[2] = {Vs0, Vs1};

    int qt = 7 - blockIdx.x;                 // heavy tiles first
    int bh = blockIdx.y;
    int b = bh >> 4, h = bh & 15;
    int len = kvlen[b];
    int tid = threadIdx.x, lane = tid & 31, wid = tid >> 5;
    int gid = lane >> 2, tig = lane & 3;
    int wr = wid >> 1, wc = wid & 1;         // warps 4x2: 32 rows x 64 cols
    int q_base = qt * 128;

    // ---- stage Q via Ks0, then keep Q fragments in registers ----
    const float* qp = g_q + ((size_t)bh << 16) + (size_t)q_base * 64;
    #pragma unroll
    for (int s = 0; s < 8; s++){
        int idx = tid + 256*s;
        int r = idx >> 4, c4 = idx & 15;
        cpa16(&Ks0[r*KS_LD + c4*4], qp + (size_t)idx*4);
    }
    cp_commit(); cp_wait0();
    __syncthreads();

    unsigned qa[2][8][4];
    #pragma unroll
    for (int i=0;i<2;i++){
        int m = wr*32 + i*16 + gid;
        #pragma unroll
        for (int kst=0;kst<8;kst++){
            qa[i][kst][0] = __float_as_uint(Ks0[m*KS_LD     + kst*8 + tig]);
            qa[i][kst][1] = __float_as_uint(Ks0[(m+8)*KS_LD + kst*8 + tig]);
            qa[i][kst][2] = __float_as_uint(Ks0[m*KS_LD     + kst*8 + tig + 4]);
            qa[i][kst][3] = __float_as_uint(Ks0[(m+8)*KS_LD + kst*8 + tig + 4]);
        }
    }
    if (tid < 128) rsum[tid] = 0.f;
    __syncthreads();

    const float* kbase = g_k + ((size_t)bh << 16);
    const float* vbase = g_v + ((size_t)bh << 16);
    auto load_kv = [&](int buf, int kt){
        const float* kp = kbase + (size_t)kt * 8192;
        const float* vp = vbase + (size_t)kt * 8192;
        #pragma unroll
        for (int s = 0; s < 8; s++){
            int idx = tid + 256*s;
            int r = idx >> 4, c4 = idx & 15;
            cpa16(&Kbuf[buf][r*KS_LD + c4*4], kp + (size_t)idx*4);
            cpa16(&Vbuf[buf][r*VS_LD + c4*4], vp + (size_t)idx*4);
        }
    };

    load_kv(0, 0);
    cp_commit();

    float oacc[2][4][4];
    #pragma unroll
    for (int i=0;i<2;i++)
      #pragma unroll
      for (int j=0;j<4;j++)
        #pragma unroll
        for (int r=0;r<4;r++) oacc[i][j][r] = 0.f;
    float part[4] = {0.f, 0.f, 0.f, 0.f};

    for (int kt = 0; kt <= qt; kt++){
        int buf = kt & 1;
        if (kt < qt){ load_kv(buf^1, kt+1); cp_commit(); cp_wait1(); }
        else cp_wait0();
        __syncthreads();

        // scores = Q @ K^T
        float sacc[2][8][4];
        #pragma unroll
        for (int i=0;i<2;i++)
          #pragma unroll
          for (int j=0;j<8;j++)
            #pragma unroll
            for (int r=0;r<4;r++) sacc[i][j][r] = 0.f;
        const float* Kb = Kbuf[buf];
        #pragma unroll
        for (int kst = 0; kst < 8; kst++){
            unsigned bfr[8][2];
            #pragma unroll
            for (int j=0;j<8;j++){
                int n = wc*64 + j*8 + gid;
                bfr[j][0] = __float_as_uint(Kb[n*KS_LD + kst*8 + tig]);
                bfr[j][1] = __float_as_uint(Kb[n*KS_LD + kst*8 + tig + 4]);
            }
            #pragma unroll
            for (int i=0;i<2;i++)
                #pragma unroll
                for (int j=0;j<8;j++)
                    MMA_TF32(sacc[i][j], qa[i][kst], bfr[j]);
        }

        // masked unnormalized exp -> Ps, accumulate rowsums
        #pragma unroll
        for (int i=0;i<2;i++){
            int r0  = wr*32 + i*16 + gid;
            int qr0 = q_base + r0, qr1 = qr0 + 8;
            #pragma unroll
            for (int j=0;j<8;j++){
                int cl = wc*64 + j*8 + 2*tig;
                int c0 = kt*128 + cl, c1 = c0 + 1;
                float p00 = (c0 <= qr0 && c0 < len) ? __expf(sacc[i][j][0]*0.125f) : 0.f;
                float p01 = (c1 <= qr0 && c1 < len) ? __expf(sacc[i][j][1]*0.125f) : 0.f;
                float p10 = (c0 <= qr1 && c0 < len) ? __expf(sacc[i][j][2]*0.125f) : 0.f;
                float p11 = (c1 <= qr1 && c1 < len) ? __expf(sacc[i][j][3]*0.125f) : 0.f;
                Ps[r0*PS_LD + cl]       = p00;
                Ps[r0*PS_LD + cl + 1]   = p01;
                Ps[(r0+8)*PS_LD + cl]   = p10;
                Ps[(r0+8)*PS_LD + cl+1] = p11;
                part[i*2+0] += p00 + p01;
                part[i*2+1] += p10 + p11;
            }
        }
        __syncthreads();

        // write unnormalized attn tile (coalesced float4)
        float* aout = attn_out + ((size_t)bh << 20) + (size_t)q_base * 1024 + kt*128;
        #pragma unroll
        for (int s = 0; s < 16; s++){
            int idx = tid + 256*s;
            int r = idx >> 5, c4 = idx & 31;
            float4 v = *(float4*)(&Ps[r*PS_LD + c4*4]);
            *(float4*)(aout + (size_t)r*1024 + c4*4) = v;
        }

        // O += P @ V
        const float* Vb = Vbuf[buf];
        #pragma unroll
        for (int ks = 0; ks < 128; ks += 8){
            unsigned a[2][4], bfr[4][2];
            #pragma unroll
            for (int i=0;i<2;i++){
                int m = wr*32 + i*16 + gid;
                a[i][0] = __float_as_uint(tf32r(Ps[m*PS_LD     + ks + tig]));
                a[i][1] = __float_as_uint(tf32r(Ps[(m+8)*PS_LD + ks + tig]));
                a[i][2] = __float_as_uint(tf32r(Ps[m*PS_LD     + ks + tig + 4]));
                a[i][3] = __float_as_uint(tf32r(Ps[(m+8)*PS_LD + ks + tig + 4]));
            }
            #pragma unroll
            for (int j=0;j<4;j++){
                int n = wc*32 + j*8 + gid;
                bfr[j][0] = __float_as_uint(Vb[(ks+tig)*VS_LD   + n]);
                bfr[j][1] = __float_as_uint(Vb[(ks+tig+4)*VS_LD + n]);
            }
            #pragma unroll
            for (int i=0;i<2;i++)
                #pragma unroll
                for (int j=0;j<4;j++)
                    MMA_TF32(oacc[i][j], a[i], bfr[j]);
        }
        __syncthreads();
    }

    // reduce rowsums
    #pragma unroll
    for (int pi = 0; pi < 4; pi++){
        float p = part[pi];
        p += __shfl_xor_sync(0xffffffffu, p, 1);
        p += __shfl_xor_sync(0xffffffffu, p, 2);
        if (tig == 0){
            int r = wr*32 + (pi >> 1)*16 + gid + (pi & 1)*8;
            atomicAdd(&rsum[r], p);
        }
    }
    __syncthreads();
    if (tid < 128){
        float iv = 1.0f / rsum[tid];
        rinv[tid] = iv;
        g_rinv[bh*SEQ + q_base + tid] = iv;
    }
    __syncthreads();

    // epilogue: seq = x + O * rinv
    #pragma unroll
    for (int i=0;i<2;i++){
        int r0 = wr*32 + i*16 + gid;
        int q0 = q_base + r0;
        float inv0 = rinv[r0], inv1 = rinv[r0 + 8];
        #pragma unroll
        for (int j=0;j<4;j++){
            int col = wc*32 + j*8 + 2*tig;
            size_t a0 = ((size_t)(b*SEQ + q0))*DMODEL + h*HD + col;
            float2 xa = *(const float2*)(x + a0);
            *(float2*)(seq + a0) = make_float2(xa.x + oacc[i][j][0]*inv0,
                                               xa.y + oacc[i][j][1]*inv0);
            size_t a1 = a0 + (size_t)8*DMODEL;
            float2 xb = *(const float2*)(x + a1);
            *(float2*)(seq + a1) = make_float2(xb.x + oacc[i][j][2]*inv1,
                                               xb.y + oacc[i][j][3]*inv1);
        }
    }
}

// ---------------- Kernel 4: normalize attn + zero-fill masked region --------
__global__ void __launch_bounds__(256) norm_kernel(float* __restrict__ attn)
{
    int bid = blockIdx.x;                 // 512
    int qt = 7 - (bid >> 6);              // heavy first
    int bh = bid & 63;
    int tid = threadIdx.x, lane = tid & 31, wid = tid >> 5;
    float* base = attn + ((size_t)bh << 20) + (size_t)qt * 128 * 1024;
    const float* rv = g_rinv + bh*SEQ + qt*128;
    int cols4 = (qt + 1) * 32;
    for (int r = wid; r < 128; r += 8){
        float inv = rv[r];
        float* row = base + (size_t)r * 1024;
        for (int c4 = lane; c4 < 256; c4 += 32){
            if (c4 < cols4){
                float4 v = *(float4*)(row + c4*4);
                v.x *= inv; v.y *= inv; v.z *= inv; v.w *= inv;
                *(float4*)(row + c4*4) = v;
            } else {
                *(float4*)(row + c4*4) = make_float4(0.f,0.f,0.f,0.f);
            }
        }
    }
}

// ---------------- launch ----------------------------------------------------
extern "C" void kernel_launch(void* const* d_in, const int* in_sizes, int n_in,
                              void* d_out, int out_size)
{
    const float* x     = (const float*)d_in[0];
    const int*   kvlen = (const int*)  d_in[3];
    const float* gamma = (const float*)d_in[4];
    const float* beta  = (const float*)d_in[5];
    const float* Wq    = (const float*)d_in[6];
    const float* bq    = (const float*)d_in[7];
    const float* Wk    = (const float*)d_in[8];
    const float* bk    = (const float*)d_in[9];
    const float* Wv    = (const float*)d_in[10];
    const float* bv    = (const float*)d_in[11];

    float* seq  = (float*)d_out;
    float* attn = seq + (size_t)BATCH*SEQ*DMODEL;

    cudaFuncSetAttribute(attn_kernel,
        cudaFuncAttributeMaxDynamicSharedMemorySize, ATTN_SMEM_BYTES);

    prep_w<<<3072, 256>>>(Wq, Wk, Wv);
    ln_kernel<<<BATCH*SEQ, 256>>>(x, gamma, beta);
    proj_kernel<<<dim3(32, 24), 256>>>(bq, bk, bv);
    attn_kernel<<<dim3(8, 64), 256, ATTN_SMEM_BYTES>>>(x, kvlen, seq, attn);
    norm_kernel<<<512, 256>>>(attn);
}

// round 4
// speedup vs baseline: 1.2105x; 1.2105x over previous
#include <cuda_runtime.h>
#include <cstdint>
#include <cstddef>

#define BATCH 4
#define SEQ   1024
#define DMODEL 1024
#define NH    16
#define HD    64

// ---------------- scratch (device globals: no runtime allocation) ----------
__device__ float g_xn[BATCH*SEQ*DMODEL];     // layernormed input, tf32-rounded
__device__ float g_wt[3*DMODEL*DMODEL];      // [Wq|Wk|Wv], tf32-rounded
__device__ float g_q[BATCH*SEQ*DMODEL];      // (B,H,S,64), tf32-rounded
__device__ float g_k[BATCH*SEQ*DMODEL];
__device__ float g_v[BATCH*SEQ*DMODEL];
__device__ float g_rinv[BATCH*NH*SEQ];       // 1/rowsum per (b,h,q)

__device__ __forceinline__ float tf32r(float f){
    unsigned u; asm("cvt.rna.tf32.f32 %0, %1;" : "=r"(u) : "f"(f));
    return __uint_as_float(u);
}

__device__ __forceinline__ void cpa16(void* dst, const void* src){
    unsigned d = (unsigned)__cvta_generic_to_shared(dst);
    asm volatile("cp.async.cg.shared.global [%0], [%1], 16;" :: "r"(d), "l"(src));
}
__device__ __forceinline__ void cp_commit(){ asm volatile("cp.async.commit_group;"); }
__device__ __forceinline__ void cp_wait0(){ asm volatile("cp.async.wait_group 0;"); }
__device__ __forceinline__ void cp_wait1(){ asm volatile("cp.async.wait_group 1;"); }

#define MMA_TF32(d, a, b_) \
  asm volatile("mma.sync.aligned.m16n8k8.row.col.f32.tf32.tf32.f32 " \
    "{%0,%1,%2,%3},{%4,%5,%6,%7},{%8,%9},{%0,%1,%2,%3};" \
    : "+f"((d)[0]),"+f"((d)[1]),"+f"((d)[2]),"+f"((d)[3]) \
    : "r"((a)[0]),"r"((a)[1]),"r"((a)[2]),"r"((a)[3]),"r"((b_)[0]),"r"((b_)[1]))

// ---------------- Kernel 0: pre-round W to tf32 ----------------------------
__global__ void __launch_bounds__(256) prep_w(const float* __restrict__ Wq,
    const float* __restrict__ Wk, const float* __restrict__ Wv)
{
    int i = blockIdx.x * 256 + threadIdx.x;          // float4 index, 786432 total
    const float* src = (i < 262144) ? Wq : (i < 524288) ? Wk : Wv;
    float4 v = ((const float4*)src)[i & 0x3FFFF];
    v.x = tf32r(v.x); v.y = tf32r(v.y); v.z = tf32r(v.z); v.w = tf32r(v.w);
    ((float4*)g_wt)[i] = v;
}

// ---------------- Kernel 1: LayerNorm (fp32 stats, tf32-rounded output) ----
__global__ void __launch_bounds__(256) ln_kernel(const float* __restrict__ x,
    const float* __restrict__ gamma, const float* __restrict__ beta)
{
    int row = blockIdx.x;
    int tid = threadIdx.x, lane = tid & 31, wid = tid >> 5;
    const float4* xr = (const float4*)(x + (size_t)row * DMODEL);
    float4 v = xr[tid];
    float s  = v.x + v.y + v.z + v.w;
    float sq = v.x*v.x + v.y*v.y + v.z*v.z + v.w*v.w;
    #pragma unroll
    for (int o = 16; o > 0; o >>= 1){
        s  += __shfl_xor_sync(0xffffffffu, s,  o);
        sq += __shfl_xor_sync(0xffffffffu, sq, o);
    }
    __shared__ float ws[8], wq[8], stat[2];
    if (lane == 0){ ws[wid] = s; wq[wid] = sq; }
    __syncthreads();
    if (wid == 0){
        float a = (lane < 8) ? ws[lane] : 0.f;
        float q = (lane < 8) ? wq[lane] : 0.f;
        #pragma unroll
        for (int o = 4; o > 0; o >>= 1){
            a += __shfl_xor_sync(0xffffffffu, a, o);
            q += __shfl_xor_sync(0xffffffffu, q, o);
        }
        if (lane == 0){
            float mean = a * (1.0f / DMODEL);
            float var  = q * (1.0f / DMODEL) - mean * mean;
            stat[0] = mean; stat[1] = rsqrtf(var + 1e-5f);
        }
    }
    __syncthreads();
    float mean = stat[0], rstd = stat[1];
    float4 g  = ((const float4*)gamma)[tid];
    float4 be = ((const float4*)beta)[tid];
    float4 y;
    y.x = tf32r((v.x - mean) * rstd * g.x + be.x);
    y.y = tf32r((v.y - mean) * rstd * g.y + be.y);
    y.z = tf32r((v.z - mean) * rstd * g.z + be.z);
    y.w = tf32r((v.w - mean) * rstd * g.w + be.w);
    ((float4*)(g_xn + (size_t)row * DMODEL))[tid] = y;
}

// ---------------- Kernel 2: QKV projection GEMM (3-stage cp.async) ---------
#define PA_LD 36
#define PB_LD 136
#define PROJ_STAGE_A (128*PA_LD)
#define PROJ_STAGE_B (32*PB_LD)
#define PROJ_SMEM_FLOATS (3*(PROJ_STAGE_A + PROJ_STAGE_B))
#define PROJ_SMEM_BYTES  (PROJ_SMEM_FLOATS*4)

__global__ void __launch_bounds__(256,2) proj_kernel(
    const float* __restrict__ bq, const float* __restrict__ bk,
    const float* __restrict__ bv)
{
    extern __shared__ float psm[];
    float* Asb = psm;                         // 3 stages of 128x32 (LD 36)
    float* Bsb = psm + 3*PROJ_STAGE_A;        // 3 stages of 32x128 (LD 136)

    int m0 = blockIdx.x * 128;
    int by = blockIdx.y;
    int wsel = by >> 3;
    int n0 = (by & 7) * 128;
    const float* W    = g_wt + (size_t)wsel * DMODEL * DMODEL;
    const float* bias = (wsel == 0) ? bq : (wsel == 1) ? bk : bv;
    float* out        = (wsel == 0) ? g_q : (wsel == 1) ? g_k : g_v;

    int tid = threadIdx.x, lane = tid & 31, wid = tid >> 5;
    int gid = lane >> 2, tig = lane & 3;
    int wr = wid >> 2, wc = wid & 3;     // warp tile: 64 rows x 32 cols

    float acc[4][4][4];
    #pragma unroll
    for (int i=0;i<4;i++)
      #pragma unroll
      for (int j=0;j<4;j++)
        #pragma unroll
        for (int r=0;r<4;r++) acc[i][j][r] = 0.f;

    auto load_stage = [&](int st, int k0){
        float* As = Asb + st*PROJ_STAGE_A;
        float* Bs = Bsb + st*PROJ_STAGE_B;
        #pragma unroll
        for (int s = 0; s < 4; s++){
            int idx = tid + 256*s;
            int r = idx >> 3, c4 = idx & 7;
            cpa16(&As[r*PA_LD + c4*4],
                  g_xn + (size_t)(m0 + r)*1024 + k0 + c4*4);
        }
        #pragma unroll
        for (int s = 0; s < 4; s++){
            int idx = tid + 256*s;
            int r = idx >> 5, c4 = idx & 31;
            cpa16(&Bs[r*PB_LD + c4*4],
                  W + (size_t)(k0 + r)*1024 + n0 + c4*4);
        }
    };

    load_stage(0, 0);  cp_commit();
    load_stage(1, 32); cp_commit();

    for (int it = 0; it < 32; it++){
        if (it < 31) cp_wait1(); else cp_wait0();
        __syncthreads();
        if (it + 2 < 32){ load_stage((it+2)%3, (it+2)*32); cp_commit(); }
        const float* As = Asb + (it%3)*PROJ_STAGE_A;
        const float* Bs = Bsb + (it%3)*PROJ_STAGE_B;
        #pragma unroll
        for (int ks = 0; ks < 32; ks += 8){
            unsigned a[4][4], bfr[4][2];
            #pragma unroll
            for (int i=0;i<4;i++){
                int m = wr*64 + i*16 + gid;
                a[i][0] = __float_as_uint(As[m*PA_LD     + ks + tig]);
                a[i][1] = __float_as_uint(As[(m+8)*PA_LD + ks + tig]);
                a[i][2] = __float_as_uint(As[m*PA_LD     + ks + tig + 4]);
                a[i][3] = __float_as_uint(As[(m+8)*PA_LD + ks + tig + 4]);
            }
            #pragma unroll
            for (int j=0;j<4;j++){
                int n = wc*32 + j*8 + gid;
                bfr[j][0] = __float_as_uint(Bs[(ks+tig)*PB_LD   + n]);
                bfr[j][1] = __float_as_uint(Bs[(ks+tig+4)*PB_LD + n]);
            }
            #pragma unroll
            for (int i=0;i<4;i++)
                #pragma unroll
                for (int j=0;j<4;j++)
                    MMA_TF32(acc[i][j], a[i], bfr[j]);
        }
        // NOTE: no trailing sync — next iteration's barrier (before any smem
        // overwrite is issued) provides the required ordering.
    }
    // epilogue: bias + tf32 round + scatter to (B,H,S,64)
    #pragma unroll
    for (int i=0;i<4;i++){
        int m  = m0 + wr*64 + i*16 + gid;
        int bb = m >> 10, s1 = m & 1023;
        #pragma unroll
        for (int j=0;j<4;j++){
            int nl = n0 + wc*32 + j*8 + 2*tig;
            int h = nl >> 6, d = nl & 63;
            size_t base = ((size_t)(bb*NH + h)*SEQ + s1)*HD + d;
            float2 v0 = make_float2(tf32r(acc[i][j][0] + bias[nl]),
                                    tf32r(acc[i][j][1] + bias[nl+1]));
            *(float2*)(out + base) = v0;
            float2 v1 = make_float2(tf32r(acc[i][j][2] + bias[nl]),
                                    tf32r(acc[i][j][3] + bias[nl+1]));
            *(float2*)(out + base + (size_t)8*HD) = v1;
        }
    }
}

// ---------------- Kernel 3: single-pass attention (512 thr, Q in smem) -----
#define QS_LD 68
#define KS_LD 68
#define VS_LD 72
#define PS_LD 132
#define ATTN_SMEM_FLOATS (128*QS_LD + 2*128*KS_LD + 128*VS_LD + 128*PS_LD + 256)
#define ATTN_SMEM_BYTES  (ATTN_SMEM_FLOATS*4)

__global__ void __launch_bounds__(512) attn_kernel(
    const float* __restrict__ x, const int* __restrict__ kvlen,
    float* __restrict__ seq, float* __restrict__ attn_out)
{
    extern __shared__ float sm[];
    float* Qs   = sm;
    float* Ks0  = Qs  + 128*QS_LD;
    float* Ks1  = Ks0 + 128*KS_LD;
    float* Vs   = Ks1 + 128*KS_LD;
    float* Ps   = Vs  + 128*VS_LD;
    float* rsum = Ps  + 128*PS_LD;
    float* rinv = rsum + 128;
    float* Kbuf[2] = {Ks0, Ks1};

    int qt = 7 - blockIdx.x;                 // heavy tiles first
    int bh = blockIdx.y;
    int b = bh >> 4, h = bh & 15;
    int len = kvlen[b];
    int tid = threadIdx.x, lane = tid & 31, wid = tid >> 5;
    int gid = lane >> 2, tig = lane & 3;
    int wr = wid >> 2, wc = wid & 3;         // 16 warps as 4x4
    int q_base = qt * 128;

    const float* qp    = g_q + ((size_t)bh << 16) + (size_t)q_base * 64;
    const float* kbase = g_k + ((size_t)bh << 16);
    const float* vbase = g_v + ((size_t)bh << 16);
    float* attn_base   = attn_out + ((size_t)bh << 20) + (size_t)q_base * 1024;

    // group 0: Q tile + K(0)
    #pragma unroll
    for (int s = 0; s < 4; s++){
        int idx = tid + 512*s;
        int r = idx >> 4, c4 = idx & 15;
        cpa16(&Qs[r*QS_LD + c4*4], qp + (size_t)idx*4);
        cpa16(&Ks0[r*KS_LD + c4*4], kbase + (size_t)idx*4);
    }
    cp_commit();

    // zero-fill fully-masked causal tiles (overlaps the loads)
    for (int kt = qt + 1; kt < 8; kt++){
        float* aout = attn_base + kt*128;
        #pragma unroll
        for (int s = 0; s < 8; s++){
            int idx = tid + 512*s;
            int r = idx >> 5, c4 = idx & 31;
            *(float4*)(aout + (size_t)r*1024 + c4*4) = make_float4(0.f,0.f,0.f,0.f);
        }
    }
    if (tid < 128) rsum[tid] = 0.f;

    float oacc[2][2][4];
    #pragma unroll
    for (int i=0;i<2;i++)
      #pragma unroll
      for (int j=0;j<2;j++)
        #pragma unroll
        for (int r=0;r<4;r++) oacc[i][j][r] = 0.f;
    float part[4] = {0.f, 0.f, 0.f, 0.f};

    for (int kt = 0; kt <= qt; kt++){
        int buf = kt & 1;
        // issue V(kt) and K(kt+1) prefetch as one group
        {
            const float* vp = vbase + (size_t)kt * 8192;
            #pragma unroll
            for (int s = 0; s < 4; s++){
                int idx = tid + 512*s;
                int r = idx >> 4, c4 = idx & 15;
                cpa16(&Vs[r*VS_LD + c4*4], vp + (size_t)idx*4);
            }
            if (kt < qt){
                const float* kp = kbase + (size_t)(kt+1) * 8192;
                #pragma unroll
                for (int s = 0; s < 4; s++){
                    int idx = tid + 512*s;
                    int r = idx >> 4, c4 = idx & 15;
                    cpa16(&Kbuf[buf^1][r*KS_LD + c4*4], kp + (size_t)idx*4);
                }
            }
            cp_commit();
        }
        cp_wait1();           // K(kt) (and Q on first iter) ready
        __syncthreads();

        // ---- scores = Q @ K^T : warp tile 32x32 ----
        float sacc[2][4][4];
        #pragma unroll
        for (int i=0;i<2;i++)
          #pragma unroll
          for (int j=0;j<4;j++)
            #pragma unroll
            for (int r=0;r<4;r++) sacc[i][j][r] = 0.f;
        const float* Kb = Kbuf[buf];
        #pragma unroll
        for (int kst = 0; kst < 8; kst++){
            unsigned a[2][4], bfr[4][2];
            #pragma unroll
            for (int i=0;i<2;i++){
                int m = wr*32 + i*16 + gid;
                a[i][0] = __float_as_uint(Qs[m*QS_LD     + kst*8 + tig]);
                a[i][1] = __float_as_uint(Qs[(m+8)*QS_LD + kst*8 + tig]);
                a[i][2] = __float_as_uint(Qs[m*QS_LD     + kst*8 + tig + 4]);
                a[i][3] = __float_as_uint(Qs[(m+8)*QS_LD + kst*8 + tig + 4]);
            }
            #pragma unroll
            for (int j=0;j<4;j++){
                int n = wc*32 + j*8 + gid;
                bfr[j][0] = __float_as_uint(Kb[n*KS_LD + kst*8 + tig]);
                bfr[j][1] = __float_as_uint(Kb[n*KS_LD + kst*8 + tig + 4]);
            }
            #pragma unroll
            for (int i=0;i<2;i++)
                #pragma unroll
                for (int j=0;j<4;j++)
                    MMA_TF32(sacc[i][j], a[i], bfr[j]);
        }

        // ---- masked unnormalized exp -> Ps, accumulate rowsums ----
        #pragma unroll
        for (int i=0;i<2;i++){
            int r0  = wr*32 + i*16 + gid;
            int qr0 = q_base + r0, qr1 = qr0 + 8;
            #pragma unroll
            for (int j=0;j<4;j++){
                int cl = wc*32 + j*8 + 2*tig;
                int c0 = kt*128 + cl, c1 = c0 + 1;
                float p00 = (c0 <= qr0 && c0 < len) ? __expf(sacc[i][j][0]*0.125f) : 0.f;
                float p01 = (c1 <= qr0 && c1 < len) ? __expf(sacc[i][j][1]*0.125f) : 0.f;
                float p10 = (c0 <= qr1 && c0 < len) ? __expf(sacc[i][j][2]*0.125f) : 0.f;
                float p11 = (c1 <= qr1 && c1 < len) ? __expf(sacc[i][j][3]*0.125f) : 0.f;
                Ps[r0*PS_LD + cl]       = p00;
                Ps[r0*PS_LD + cl + 1]   = p01;
                Ps[(r0+8)*PS_LD + cl]   = p10;
                Ps[(r0+8)*PS_LD + cl+1] = p11;
                part[i*2+0] += p00 + p01;
                part[i*2+1] += p10 + p11;
            }
        }
        __syncthreads();

        // write unnormalized attn tile (coalesced float4)
        {
            float* aout = attn_base + kt*128;
            #pragma unroll
            for (int s = 0; s < 8; s++){
                int idx = tid + 512*s;
                int r = idx >> 5, c4 = idx & 31;
                float4 v = *(float4*)(&Ps[r*PS_LD + c4*4]);
                *(float4*)(aout + (size_t)r*1024 + c4*4) = v;
            }
        }

        cp_wait0();           // V(kt) ready (K(kt+1) also lands; fine)
        __syncthreads();

        // ---- O += P @ V : warp tile 32x16 ----
        #pragma unroll
        for (int ks = 0; ks < 128; ks += 8){
            unsigned a[2][4], bfr[2][2];
            #pragma unroll
            for (int i=0;i<2;i++){
                int m = wr*32 + i*16 + gid;
                a[i][0] = __float_as_uint(tf32r(Ps[m*PS_LD     + ks + tig]));
                a[i][1] = __float_as_uint(tf32r(Ps[(m+8)*PS_LD + ks + tig]));
                a[i][2] = __float_as_uint(tf32r(Ps[m*PS_LD     + ks + tig + 4]));
                a[i][3] = __float_as_uint(tf32r(Ps[(m+8)*PS_LD + ks + tig + 4]));
            }
            #pragma unroll
            for (int j=0;j<2;j++){
                int n = wc*16 + j*8 + gid;
                bfr[j][0] = __float_as_uint(Vs[(ks+tig)*VS_LD   + n]);
                bfr[j][1] = __float_as_uint(Vs[(ks+tig+4)*VS_LD + n]);
            }
            #pragma unroll
            for (int i=0;i<2;i++)
                #pragma unroll
                for (int j=0;j<2;j++)
                    MMA_TF32(oacc[i][j], a[i], bfr[j]);
        }
        __syncthreads();      // Ps/Vs free for next iter
    }

    // reduce rowsums
    #pragma unroll
    for (int pi = 0; pi < 4; pi++){
        float p = part[pi];
        p += __shfl_xor_sync(0xffffffffu, p, 1);
        p += __shfl_xor_sync(0xffffffffu, p, 2);
        if (tig == 0){
            int r = wr*32 + (pi >> 1)*16 + gid + (pi & 1)*8;
            atomicAdd(&rsum[r], p);
        }
    }
    __syncthreads();
    if (tid < 128){
        float iv = 1.0f / rsum[tid];
        rinv[tid] = iv;
        g_rinv[bh*SEQ + q_base + tid] = iv;
    }
    __syncthreads();

    // epilogue: seq = x + O * rinv
    #pragma unroll
    for (int i=0;i<2;i++){
        int r0 = wr*32 + i*16 + gid;
        int q0 = q_base + r0;
        float inv0 = rinv[r0], inv1 = rinv[r0 + 8];
        #pragma unroll
        for (int j=0;j<2;j++){
            int col = wc*16 + j*8 + 2*tig;
            size_t a0 = ((size_t)(b*SEQ + q0))*DMODEL + h*HD + col;
            float2 xa = *(const float2*)(x + a0);
            *(float2*)(seq + a0) = make_float2(xa.x + oacc[i][j][0]*inv0,
                                               xa.y + oacc[i][j][1]*inv0);
            size_t a1 = a0 + (size_t)8*DMODEL;
            float2 xb = *(const float2*)(x + a1);
            *(float2*)(seq + a1) = make_float2(xb.x + oacc[i][j][2]*inv1,
                                               xb.y + oacc[i][j][3]*inv1);
        }
    }
}

// ---------------- Kernel 4: normalize causal attn tiles ---------------------
__global__ void __launch_bounds__(256) norm_kernel(float* __restrict__ attn)
{
    int bid = blockIdx.x;                 // 64*36 = 2304 causal tiles
    int bh = bid & 63;
    int t  = bid >> 6;                    // 0..35 triangular index
    int qt = 0;
    #pragma unroll
    for (int q = 7; q >= 1; q--) if (t >= (q*(q+1))/2){ qt = q; break; }
    int kt = t - (qt*(qt+1))/2;

    int tid = threadIdx.x, lane = tid & 31;
    float* base = attn + ((size_t)bh << 20) + ((size_t)qt*128*1024) + kt*128;
    const float* rv = g_rinv + bh*SEQ + qt*128;
    #pragma unroll
    for (int s = 0; s < 16; s++){
        int r = (tid >> 5) + 8*s;
        float inv = rv[r];
        float* row = base + (size_t)r * 1024;
        float4 v = *(float4*)(row + lane*4);
        v.x *= inv; v.y *= inv; v.z *= inv; v.w *= inv;
        *(float4*)(row + lane*4) = v;
    }
}

// ---------------- launch ----------------------------------------------------
extern "C" void kernel_launch(void* const* d_in, const int* in_sizes, int n_in,
                              void* d_out, int out_size)
{
    const float* x     = (const float*)d_in[0];
    const int*   kvlen = (const int*)  d_in[3];
    const float* gamma = (const float*)d_in[4];
    const float* beta  = (const float*)d_in[5];
    const float* Wq    = (const float*)d_in[6];
    const float* bq    = (const float*)d_in[7];
    const float* Wk    = (const float*)d_in[8];
    const float* bk    = (const float*)d_in[9];
    const float* Wv    = (const float*)d_in[10];
    const float* bv    = (const float*)d_in[11];

    float* seq  = (float*)d_out;
    float* attn = seq + (size_t)BATCH*SEQ*DMODEL;

    cudaFuncSetAttribute(proj_kernel,
        cudaFuncAttributeMaxDynamicSharedMemorySize, PROJ_SMEM_BYTES);
    cudaFuncSetAttribute(attn_kernel,
        cudaFuncAttributeMaxDynamicSharedMemorySize, ATTN_SMEM_BYTES);

    prep_w<<<3072, 256>>>(Wq, Wk, Wv);
    ln_kernel<<<BATCH*SEQ, 256>>>(x, gamma, beta);
    proj_kernel<<<dim3(32, 24), 256, PROJ_SMEM_BYTES>>>(bq, bk, bv);
    attn_kernel<<<dim3(8, 64), 512, ATTN_SMEM_BYTES>>>(x, kvlen, seq, attn);
    norm_kernel<<<2304, 256>>>(attn);
}

// round 5
// speedup vs baseline: 1.2989x; 1.0730x over previous
#include <cuda_runtime.h>
#include <cstdint>
#include <cstddef>

#define BATCH 4
#define SEQ   1024
#define DMODEL 1024
#define NH    16
#define HD    64

// ---------------- scratch (device globals: no runtime allocation) ----------
__device__ float g_xn[BATCH*SEQ*DMODEL];     // layernormed input, tf32-rounded
__device__ float g_wt[3*DMODEL*DMODEL];      // W^T per slice: [n][k], tf32-rounded
__device__ float g_q[BATCH*SEQ*DMODEL];      // (B,H,S,64), tf32-rounded
__device__ float g_k[BATCH*SEQ*DMODEL];      // (B,H,S,64), tf32-rounded
__device__ float g_v[BATCH*SEQ*DMODEL];      // TRANSPOSED: (B,H,64,S), tf32-rounded

__device__ __forceinline__ float tf32r(float f){
    unsigned u; asm("cvt.rna.tf32.f32 %0, %1;" : "=r"(u) : "f"(f));
    return __uint_as_float(u);
}

__device__ __forceinline__ void cpa16(void* dst, const void* src){
    unsigned d = (unsigned)__cvta_generic_to_shared(dst);
    asm volatile("cp.async.cg.shared.global [%0], [%1], 16;" :: "r"(d), "l"(src));
}
__device__ __forceinline__ void cp_commit(){ asm volatile("cp.async.commit_group;"); }
__device__ __forceinline__ void cp_wait0(){ asm volatile("cp.async.wait_group 0;"); }
__device__ __forceinline__ void cp_wait1(){ asm volatile("cp.async.wait_group 1;"); }

// ldmatrix x4: loads 4 8x8 b16 matrices == tf32 16x8 (A) or two k8n8 (B) frags
__device__ __forceinline__ void ldsm4(unsigned* r, unsigned addr){
    asm volatile("ldmatrix.sync.aligned.m8n8.x4.shared.b16 {%0,%1,%2,%3}, [%4];"
        : "=r"(r[0]),"=r"(r[1]),"=r"(r[2]),"=r"(r[3]) : "r"(addr));
}

#define MMA_TF32(d, a, b_) \
  asm volatile("mma.sync.aligned.m16n8k8.row.col.f32.tf32.tf32.f32 " \
    "{%0,%1,%2,%3},{%4,%5,%6,%7},{%8,%9},{%0,%1,%2,%3};" \
    : "+f"((d)[0]),"+f"((d)[1]),"+f"((d)[2]),"+f"((d)[3]) \
    : "r"((a)[0]),"r"((a)[1]),"r"((a)[2]),"r"((a)[3]),"r"((b_)[0]),"r"((b_)[1]))

// ---------------- Kernel 0: round W to tf32 AND transpose -> [n][k] --------
__global__ void __launch_bounds__(256) prep_w(const float* __restrict__ Wq,
    const float* __restrict__ Wk, const float* __restrict__ Wv)
{
    __shared__ float t[64][65];
    int w = blockIdx.z;
    const float* W = (w == 0) ? Wq : (w == 1) ? Wk : Wv;
    float* out = g_wt + (size_t)w * DMODEL * DMODEL;
    int kb = blockIdx.y * 64, nb = blockIdx.x * 64;
    int tid = threadIdx.x;
    #pragma unroll
    for (int i = 0; i < 4; i++){
        int idx = tid + 256*i;
        int r = idx >> 4, c4 = idx & 15;
        float4 v = *(const float4*)(W + (size_t)(kb + r)*1024 + nb + c4*4);
        t[r][c4*4+0] = tf32r(v.x); t[r][c4*4+1] = tf32r(v.y);
        t[r][c4*4+2] = tf32r(v.z); t[r][c4*4+3] = tf32r(v.w);
    }
    __syncthreads();
    #pragma unroll
    for (int i = 0; i < 4; i++){
        int idx = tid + 256*i;
        int n = idx >> 4, k4 = idx & 15;
        float4 v = make_float4(t[k4*4+0][n], t[k4*4+1][n], t[k4*4+2][n], t[k4*4+3][n]);
        *(float4*)(out + (size_t)(nb + n)*1024 + kb + k4*4) = v;
    }
}

// ---------------- Kernel 1: LayerNorm (fp32 stats, tf32-rounded output) ----
__global__ void __launch_bounds__(256) ln_kernel(const float* __restrict__ x,
    const float* __restrict__ gamma, const float* __restrict__ beta)
{
    int row = blockIdx.x;
    int tid = threadIdx.x, lane = tid & 31, wid = tid >> 5;
    const float4* xr = (const float4*)(x + (size_t)row * DMODEL);
    float4 v = xr[tid];
    float s  = v.x + v.y + v.z + v.w;
    float sq = v.x*v.x + v.y*v.y + v.z*v.z + v.w*v.w;
    #pragma unroll
    for (int o = 16; o > 0; o >>= 1){
        s  += __shfl_xor_sync(0xffffffffu, s,  o);
        sq += __shfl_xor_sync(0xffffffffu, sq, o);
    }
    __shared__ float ws[8], wq[8], stat[2];
    if (lane == 0){ ws[wid] = s; wq[wid] = sq; }
    __syncthreads();
    if (wid == 0){
        float a = (lane < 8) ? ws[lane] : 0.f;
        float q = (lane < 8) ? wq[lane] : 0.f;
        #pragma unroll
        for (int o = 4; o > 0; o >>= 1){
            a += __shfl_xor_sync(0xffffffffu, a, o);
            q += __shfl_xor_sync(0xffffffffu, q, o);
        }
        if (lane == 0){
            float mean = a * (1.0f / DMODEL);
            float var  = q * (1.0f / DMODEL) - mean * mean;
            stat[0] = mean; stat[1] = rsqrtf(var + 1e-5f);
        }
    }
    __syncthreads();
    float mean = stat[0], rstd = stat[1];
    float4 g  = ((const float4*)gamma)[tid];
    float4 be = ((const float4*)beta)[tid];
    float4 y;
    y.x = tf32r((v.x - mean) * rstd * g.x + be.x);
    y.y = tf32r((v.y - mean) * rstd * g.y + be.y);
    y.z = tf32r((v.z - mean) * rstd * g.z + be.z);
    y.w = tf32r((v.w - mean) * rstd * g.w + be.w);
    ((float4*)(g_xn + (size_t)row * DMODEL))[tid] = y;
}

// ---------------- Kernel 2: QKV projection GEMM (LDSM + 3-stage cp.async) --
#define PA_LD 36
#define PB_LD 36
#define PROJ_STAGE_A (128*PA_LD)
#define PROJ_STAGE_B (128*PB_LD)
#define PROJ_SMEM_FLOATS (3*(PROJ_STAGE_A + PROJ_STAGE_B))
#define PROJ_SMEM_BYTES  (PROJ_SMEM_FLOATS*4)

__global__ void __launch_bounds__(256,2) proj_kernel(
    const float* __restrict__ bq, const float* __restrict__ bk,
    const float* __restrict__ bv)
{
    extern __shared__ float psm[];
    float* Asb = psm;                         // 3 stages of 128(m) x 32(k)
    float* Bsb = psm + 3*PROJ_STAGE_A;        // 3 stages of 128(n) x 32(k)

    int m0 = blockIdx.x * 128;
    int by = blockIdx.y;
    int wsel = by >> 3;
    int n0 = (by & 7) * 128;
    const float* W    = g_wt + (size_t)wsel * DMODEL * DMODEL;   // [n][k]
    const float* bias = (wsel == 0) ? bq : (wsel == 1) ? bk : bv;
    float* out        = (wsel == 0) ? g_q : (wsel == 1) ? g_k : g_v;

    int tid = threadIdx.x, lane = tid & 31, wid = tid >> 5;
    int gid = lane >> 2, tig = lane & 3;
    int wr = wid >> 2, wc = wid & 3;     // warp tile: 64 rows x 32 cols
    int aRow = lane & 15,                aCol = (lane & 16) ? 4 : 0;
    int bRow = ((lane & 16) ? 8 : 0) | (lane & 7), bCol = (lane & 8) ? 4 : 0;

    unsigned As_u = (unsigned)__cvta_generic_to_shared(Asb);
    unsigned Bs_u = (unsigned)__cvta_generic_to_shared(Bsb);

    float acc[4][4][4];
    #pragma unroll
    for (int i=0;i<4;i++)
      #pragma unroll
      for (int j=0;j<4;j++)
        #pragma unroll
        for (int r=0;r<4;r++) acc[i][j][r] = 0.f;

    auto load_stage = [&](int st, int k0){
        float* As = Asb + st*PROJ_STAGE_A;
        float* Bs = Bsb + st*PROJ_STAGE_B;
        #pragma unroll
        for (int s = 0; s < 4; s++){
            int idx = tid + 256*s;
            int r = idx >> 3, c4 = idx & 7;
            cpa16(&As[r*PA_LD + c4*4],
                  g_xn + (size_t)(m0 + r)*1024 + k0 + c4*4);
            cpa16(&Bs[r*PB_LD + c4*4],
                  W + (size_t)(n0 + r)*1024 + k0 + c4*4);
        }
    };

    load_stage(0, 0);  cp_commit();
    load_stage(1, 32); cp_commit();

    for (int it = 0; it < 32; it++){
        if (it < 31) cp_wait1(); else cp_wait0();
        __syncthreads();
        if (it + 2 < 32){ load_stage((it+2)%3, (it+2)*32); cp_commit(); }
        unsigned Asu = As_u + (unsigned)((it%3)*PROJ_STAGE_A*4);
        unsigned Bsu = Bs_u + (unsigned)((it%3)*PROJ_STAGE_B*4);
        #pragma unroll
        for (int ks = 0; ks < 32; ks += 8){
            unsigned afr[4][4], bfr[2][4];
            #pragma unroll
            for (int i=0;i<4;i++)
                ldsm4(afr[i], Asu + (((wr*64+i*16+aRow)*PA_LD + ks + aCol)<<2));
            #pragma unroll
            for (int jj=0;jj<2;jj++)
                ldsm4(bfr[jj], Bsu + (((wc*32+jj*16+bRow)*PB_LD + ks + bCol)<<2));
            #pragma unroll
            for (int i=0;i<4;i++)
                #pragma unroll
                for (int j=0;j<4;j++)
                    MMA_TF32(acc[i][j], afr[i], &bfr[j>>1][(j&1)*2]);
        }
    }
    // epilogue: bias + tf32 round + scatter (Q/K: (B,H,S,64); V: (B,H,64,S))
    #pragma unroll
    for (int i=0;i<4;i++){
        int m  = m0 + wr*64 + i*16 + gid;
        int bb = m >> 10, s1 = m & 1023;
        #pragma unroll
        for (int j=0;j<4;j++){
            int nl = n0 + wc*32 + j*8 + 2*tig;
            int h = nl >> 6, d = nl & 63;
            float c0 = tf32r(acc[i][j][0] + bias[nl]);
            float c1 = tf32r(acc[i][j][1] + bias[nl+1]);
            float c2 = tf32r(acc[i][j][2] + bias[nl]);
            float c3 = tf32r(acc[i][j][3] + bias[nl+1]);
            if (wsel < 2){
                size_t base = ((size_t)(bb*NH + h)*SEQ + s1)*HD + d;
                *(float2*)(out + base) = make_float2(c0, c1);
                *(float2*)(out + base + (size_t)8*HD) = make_float2(c2, c3);
            } else {
                size_t base = ((size_t)(bb*NH + h)*HD + d)*SEQ + s1;
                out[base]            = c0;
                out[base + SEQ]      = c1;
                out[base + 8]        = c2;
                out[base + SEQ + 8]  = c3;
            }
        }
    }
}

// ---------------- Kernel 3: single-pass attention + fused normalize --------
#define QS_LD 68
#define KS_LD 68
#define VT_LD 132
#define PS_LD 132
#define ATTN_SMEM_FLOATS (128*QS_LD + 2*128*KS_LD + 64*VT_LD + 128*PS_LD + 256)
#define ATTN_SMEM_BYTES  (ATTN_SMEM_FLOATS*4)

__global__ void __launch_bounds__(512) attn_kernel(
    const float* __restrict__ x, const int* __restrict__ kvlen,
    float* __restrict__ seq, float* __restrict__ attn_out)
{
    extern __shared__ float sm[];
    float* Qs   = sm;
    float* Ks0  = Qs  + 128*QS_LD;
    float* Ks1  = Ks0 + 128*KS_LD;
    float* Vt   = Ks1 + 128*KS_LD;
    float* Ps   = Vt  + 64*VT_LD;
    float* rsum = Ps  + 128*PS_LD;
    float* rinv = rsum + 128;
    float* Kbuf[2] = {Ks0, Ks1};

    int bh = blockIdx.x;
    int qt = 7 - blockIdx.y;                 // heavy tiles first
    int b = bh >> 4, h = bh & 15;
    int len = kvlen[b];
    int tid = threadIdx.x, lane = tid & 31, wid = tid >> 5;
    int gid = lane >> 2, tig = lane & 3;
    int wr = wid >> 2, wc = wid & 3;         // 16 warps as 4x4
    int q_base = qt * 128;
    int aRow = lane & 15,                aCol = (lane & 16) ? 4 : 0;
    int bRow = ((lane & 16) ? 8 : 0) | (lane & 7), bCol = (lane & 8) ? 4 : 0;

    unsigned Qs_u = (unsigned)__cvta_generic_to_shared(Qs);
    unsigned Ks_u[2] = {(unsigned)__cvta_generic_to_shared(Ks0),
                        (unsigned)__cvta_generic_to_shared(Ks1)};
    unsigned Vt_u = (unsigned)__cvta_generic_to_shared(Vt);
    unsigned Ps_u = (unsigned)__cvta_generic_to_shared(Ps);

    const float* qp    = g_q + ((size_t)bh << 16) + (size_t)q_base * 64;
    const float* kbase = g_k + ((size_t)bh << 16);
    const float* vbase = g_v + ((size_t)bh << 16);   // (64, SEQ) transposed
    float* attn_base   = attn_out + ((size_t)bh << 20) + (size_t)q_base * 1024;

    // group 0: Q tile + K(0)
    #pragma unroll
    for (int s = 0; s < 4; s++){
        int idx = tid + 512*s;
        int r = idx >> 4, c4 = idx & 15;
        cpa16(&Qs[r*QS_LD + c4*4], qp + (size_t)idx*4);
        cpa16(&Ks0[r*KS_LD + c4*4], kbase + (size_t)idx*4);
    }
    cp_commit();

    // zero-fill fully-masked causal tiles (overlaps the loads)
    for (int kt = qt + 1; kt < 8; kt++){
        float* aout = attn_base + kt*128;
        #pragma unroll
        for (int s = 0; s < 8; s++){
            int idx = tid + 512*s;
            int r = idx >> 5, c4 = idx & 31;
            *(float4*)(aout + (size_t)r*1024 + c4*4) = make_float4(0.f,0.f,0.f,0.f);
        }
    }
    if (tid < 128) rsum[tid] = 0.f;

    float oacc[2][2][4];
    #pragma unroll
    for (int i=0;i<2;i++)
      #pragma unroll
      for (int j=0;j<2;j++)
        #pragma unroll
        for (int r=0;r<4;r++) oacc[i][j][r] = 0.f;
    float part[4] = {0.f, 0.f, 0.f, 0.f};

    for (int kt = 0; kt <= qt; kt++){
        int buf = kt & 1;
        // issue V^T(kt) and K(kt+1) prefetch as one group
        {
            const float* vp = vbase + (size_t)kt * 128;   // col offset in (64,SEQ)
            #pragma unroll
            for (int s = 0; s < 4; s++){
                int idx = tid + 512*s;
                int r = idx >> 5, c4 = idx & 31;          // 64 rows x 128 cols
                cpa16(&Vt[r*VT_LD + c4*4], vp + (size_t)r*SEQ + c4*4);
            }
            if (kt < qt){
                const float* kp = kbase + (size_t)(kt+1) * 8192;
                #pragma unroll
                for (int s = 0; s < 4; s++){
                    int idx = tid + 512*s;
                    int r = idx >> 4, c4 = idx & 15;
                    cpa16(&Kbuf[buf^1][r*KS_LD + c4*4], kp + (size_t)idx*4);
                }
            }
            cp_commit();
        }
        cp_wait1();           // K(kt) (and Q on first iter) ready
        __syncthreads();

        // ---- scores = Q @ K^T : warp tile 32x32 (LDSM) ----
        float sacc[2][4][4];
        #pragma unroll
        for (int i=0;i<2;i++)
          #pragma unroll
          for (int j=0;j<4;j++)
            #pragma unroll
            for (int r=0;r<4;r++) sacc[i][j][r] = 0.f;
        unsigned Kbu = Ks_u[buf];
        #pragma unroll
        for (int kst = 0; kst < 8; kst++){
            unsigned afr[2][4], bfr[2][4];
            #pragma unroll
            for (int i=0;i<2;i++)
                ldsm4(afr[i], Qs_u + (((wr*32+i*16+aRow)*QS_LD + kst*8 + aCol)<<2));
            #pragma unroll
            for (int jj=0;jj<2;jj++)
                ldsm4(bfr[jj], Kbu + (((wc*32+jj*16+bRow)*KS_LD + kst*8 + bCol)<<2));
            #pragma unroll
            for (int i=0;i<2;i++)
                #pragma unroll
                for (int j=0;j<4;j++)
                    MMA_TF32(sacc[i][j], afr[i], &bfr[j>>1][(j&1)*2]);
        }

        // ---- masked unnormalized exp -> Ps (tf32-rounded), rowsums ----
        #pragma unroll
        for (int i=0;i<2;i++){
            int r0  = wr*32 + i*16 + gid;
            int qr0 = q_base + r0, qr1 = qr0 + 8;
            #pragma unroll
            for (int j=0;j<4;j++){
                int cl = wc*32 + j*8 + 2*tig;
                int c0 = kt*128 + cl, c1 = c0 + 1;
                float p00 = (c0 <= qr0 && c0 < len) ? __expf(sacc[i][j][0]*0.125f) : 0.f;
                float p01 = (c1 <= qr0 && c1 < len) ? __expf(sacc[i][j][1]*0.125f) : 0.f;
                float p10 = (c0 <= qr1 && c0 < len) ? __expf(sacc[i][j][2]*0.125f) : 0.f;
                float p11 = (c1 <= qr1 && c1 < len) ? __expf(sacc[i][j][3]*0.125f) : 0.f;
                Ps[r0*PS_LD + cl]       = tf32r(p00);
                Ps[r0*PS_LD + cl + 1]   = tf32r(p01);
                Ps[(r0+8)*PS_LD + cl]   = tf32r(p10);
                Ps[(r0+8)*PS_LD + cl+1] = tf32r(p11);
                part[i*2+0] += p00 + p01;
                part[i*2+1] += p10 + p11;
            }
        }
        cp_wait0();           // V^T(kt) ready (and K(kt+1))
        __syncthreads();      // Ps visible + V visible

        // write unnormalized attn tile (except the last: handled in tail)
        if (kt < qt){
            float* aout = attn_base + kt*128;
            #pragma unroll
            for (int s = 0; s < 8; s++){
                int idx = tid + 512*s;
                int r = idx >> 5, c4 = idx & 31;
                float4 v = *(float4*)(&Ps[r*PS_LD + c4*4]);
                *(float4*)(aout + (size_t)r*1024 + c4*4) = v;
            }
        }

        // ---- O += P @ V : warp tile 32x16 (LDSM) ----
        #pragma unroll
        for (int ks = 0; ks < 128; ks += 8){
            unsigned afr[2][4], bfr[4];
            #pragma unroll
            for (int i=0;i<2;i++)
                ldsm4(afr[i], Ps_u + (((wr*32+i*16+aRow)*PS_LD + ks + aCol)<<2));
            ldsm4(bfr, Vt_u + (((wc*16+bRow)*VT_LD + ks + bCol)<<2));
            #pragma unroll
            for (int i=0;i<2;i++){
                MMA_TF32(oacc[i][0], afr[i], &bfr[0]);
                MMA_TF32(oacc[i][1], afr[i], &bfr[2]);
            }
        }
        __syncthreads();      // Ps/Vt/K free for next iter
    }

    // reduce rowsums
    #pragma unroll
    for (int pi = 0; pi < 4; pi++){
        float p = part[pi];
        p += __shfl_xor_sync(0xffffffffu, p, 1);
        p += __shfl_xor_sync(0xffffffffu, p, 2);
        if (tig == 0){
            int r = wr*32 + (pi >> 1)*16 + gid + (pi & 1)*8;
            atomicAdd(&rsum[r], p);
        }
    }
    __syncthreads();
    if (tid < 128) rinv[tid] = 1.0f / rsum[tid];
    __syncthreads();

    // tail 1: write last tile normalized, directly from Ps
    {
        float* aout = attn_base + qt*128;
        #pragma unroll
        for (int s = 0; s < 8; s++){
            int idx = tid + 512*s;
            int r = idx >> 5, c4 = idx & 31;
            float inv = rinv[r];
            float4 v = *(float4*)(&Ps[r*PS_LD + c4*4]);
            v.x *= inv; v.y *= inv; v.z *= inv; v.w *= inv;
            *(float4*)(aout + (size_t)r*1024 + c4*4) = v;
        }
    }
    // tail 2: rescale earlier tiles (mostly L2-resident: we just wrote them)
    for (int kt = 0; kt < qt; kt++){
        float* aout = attn_base + kt*128;
        #pragma unroll
        for (int s = 0; s < 8; s++){
            int idx = tid + 512*s;
            int r = idx >> 5, c4 = idx & 31;
            float inv = rinv[r];
            float4 v = *(float4*)(aout + (size_t)r*1024 + c4*4);
            v.x *= inv; v.y *= inv; v.z *= inv; v.w *= inv;
            *(float4*)(aout + (size_t)r*1024 + c4*4) = v;
        }
    }

    // epilogue: seq = x + O * rinv
    #pragma unroll
    for (int i=0;i<2;i++){
        int r0 = wr*32 + i*16 + gid;
        int q0 = q_base + r0;
        float inv0 = rinv[r0], inv1 = rinv[r0 + 8];
        #pragma unroll
        for (int j=0;j<2;j++){
            int col = wc*16 + j*8 + 2*tig;
            size_t a0 = ((size_t)(b*SEQ + q0))*DMODEL + h*HD + col;
            float2 xa = *(const float2*)(x + a0);
            *(float2*)(seq + a0) = make_float2(xa.x + oacc[i][j][0]*inv0,
                                               xa.y + oacc[i][j][1]*inv0);
            size_t a1 = a0 + (size_t)8*DMODEL;
            float2 xb = *(const float2*)(x + a1);
            *(float2*)(seq + a1) = make_float2(xb.x + oacc[i][j][2]*inv1,
                                               xb.y + oacc[i][j][3]*inv1);
        }
    }
}

// ---------------- launch ----------------------------------------------------
extern "C" void kernel_launch(void* const* d_in, const int* in_sizes, int n_in,
                              void* d_out, int out_size)
{
    const float* x     = (const float*)d_in[0];
    const int*   kvlen = (const int*)  d_in[3];
    const float* gamma = (const float*)d_in[4];
    const float* beta  = (const float*)d_in[5];
    const float* Wq    = (const float*)d_in[6];
    const float* bq    = (const float*)d_in[7];
    const float* Wk    = (const float*)d_in[8];
    const float* bk    = (const float*)d_in[9];
    const float* Wv    = (const float*)d_in[10];
    const float* bv    = (const float*)d_in[11];

    float* seq  = (float*)d_out;
    float* attn = seq + (size_t)BATCH*SEQ*DMODEL;

    cudaFuncSetAttribute(proj_kernel,
        cudaFuncAttributeMaxDynamicSharedMemorySize, PROJ_SMEM_BYTES);
    cudaFuncSetAttribute(attn_kernel,
        cudaFuncAttributeMaxDynamicSharedMemorySize, ATTN_SMEM_BYTES);

    prep_w<<<dim3(16,16,3), 256>>>(Wq, Wk, Wv);
    ln_kernel<<<BATCH*SEQ, 256>>>(x, gamma, beta);
    proj_kernel<<<dim3(32, 24), 256, PROJ_SMEM_BYTES>>>(bq, bk, bv);
    attn_kernel<<<dim3(64, 8), 512, ATTN_SMEM_BYTES>>>(x, kvlen, seq, attn);
}

// round 6
// speedup vs baseline: 1.4156x; 1.0898x over previous
#include <cuda_runtime.h>
#include <cstdint>
#include <cstddef>

#define BATCH 4
#define SEQ   1024
#define DMODEL 1024
#define NH    16
#define HD    64

// ---------------- scratch (device globals: no runtime allocation) ----------
__device__ float g_xn[BATCH*SEQ*DMODEL];     // layernormed input, tf32-rounded
__device__ float g_wt[3*DMODEL*DMODEL];      // W^T per slice: [n][k], tf32-rounded
__device__ float g_q[BATCH*SEQ*DMODEL];      // (B,H,S,64), tf32-rounded
__device__ float g_k[BATCH*SEQ*DMODEL];      // (B,H,S,64), tf32-rounded
__device__ float g_v[BATCH*SEQ*DMODEL];      // TRANSPOSED: (B,H,64,S), tf32-rounded
__device__ float g_rinv[BATCH*NH*SEQ];       // 1/rowsum per (b,h,q)

__device__ __forceinline__ float tf32r(float f){
    unsigned u; asm("cvt.rna.tf32.f32 %0, %1;" : "=r"(u) : "f"(f));
    return __uint_as_float(u);
}

__device__ __forceinline__ void cpa16(void* dst, const void* src){
    unsigned d = (unsigned)__cvta_generic_to_shared(dst);
    asm volatile("cp.async.cg.shared.global [%0], [%1], 16;" :: "r"(d), "l"(src));
}
__device__ __forceinline__ void cp_commit(){ asm volatile("cp.async.commit_group;"); }
__device__ __forceinline__ void cp_wait0(){ asm volatile("cp.async.wait_group 0;"); }
__device__ __forceinline__ void cp_wait1(){ asm volatile("cp.async.wait_group 1;"); }

__device__ __forceinline__ void ldsm4(unsigned* r, unsigned addr){
    asm volatile("ldmatrix.sync.aligned.m8n8.x4.shared.b16 {%0,%1,%2,%3}, [%4];"
        : "=r"(r[0]),"=r"(r[1]),"=r"(r[2]),"=r"(r[3]) : "r"(addr));
}

#define MMA_TF32(d, a, b_) \
  asm volatile("mma.sync.aligned.m16n8k8.row.col.f32.tf32.tf32.f32 " \
    "{%0,%1,%2,%3},{%4,%5,%6,%7},{%8,%9},{%0,%1,%2,%3};" \
    : "+f"((d)[0]),"+f"((d)[1]),"+f"((d)[2]),"+f"((d)[3]) \
    : "r"((a)[0]),"r"((a)[1]),"r"((a)[2]),"r"((a)[3]),"r"((b_)[0]),"r"((b_)[1]))

// ---------------- Kernel 0: round W to tf32 AND transpose -> [n][k] --------
__global__ void __launch_bounds__(256) prep_w(const float* __restrict__ Wq,
    const float* __restrict__ Wk, const float* __restrict__ Wv)
{
    __shared__ float t[64][65];
    int w = blockIdx.z;
    const float* W = (w == 0) ? Wq : (w == 1) ? Wk : Wv;
    float* out = g_wt + (size_t)w * DMODEL * DMODEL;
    int kb = blockIdx.y * 64, nb = blockIdx.x * 64;
    int tid = threadIdx.x;
    #pragma unroll
    for (int i = 0; i < 4; i++){
        int idx = tid + 256*i;
        int r = idx >> 4, c4 = idx & 15;
        float4 v = *(const float4*)(W + (size_t)(kb + r)*1024 + nb + c4*4);
        t[r][c4*4+0] = tf32r(v.x); t[r][c4*4+1] = tf32r(v.y);
        t[r][c4*4+2] = tf32r(v.z); t[r][c4*4+3] = tf32r(v.w);
    }
    __syncthreads();
    #pragma unroll
    for (int i = 0; i < 4; i++){
        int idx = tid + 256*i;
        int n = idx >> 4, k4 = idx & 15;
        float4 v = make_float4(t[k4*4+0][n], t[k4*4+1][n], t[k4*4+2][n], t[k4*4+3][n]);
        *(float4*)(out + (size_t)(nb + n)*1024 + kb + k4*4) = v;
    }
}

// ---------------- Kernel 1: LayerNorm (fp32 stats, tf32-rounded output) ----
__global__ void __launch_bounds__(256) ln_kernel(const float* __restrict__ x,
    const float* __restrict__ gamma, const float* __restrict__ beta)
{
    int row = blockIdx.x;
    int tid = threadIdx.x, lane = tid & 31, wid = tid >> 5;
    const float4* xr = (const float4*)(x + (size_t)row * DMODEL);
    float4 v = xr[tid];
    float s  = v.x + v.y + v.z + v.w;
    float sq = v.x*v.x + v.y*v.y + v.z*v.z + v.w*v.w;
    #pragma unroll
    for (int o = 16; o > 0; o >>= 1){
        s  += __shfl_xor_sync(0xffffffffu, s,  o);
        sq += __shfl_xor_sync(0xffffffffu, sq, o);
    }
    __shared__ float ws[8], wq[8], stat[2];
    if (lane == 0){ ws[wid] = s; wq[wid] = sq; }
    __syncthreads();
    if (wid == 0){
        float a = (lane < 8) ? ws[lane] : 0.f;
        float q = (lane < 8) ? wq[lane] : 0.f;
        #pragma unroll
        for (int o = 4; o > 0; o >>= 1){
            a += __shfl_xor_sync(0xffffffffu, a, o);
            q += __shfl_xor_sync(0xffffffffu, q, o);
        }
        if (lane == 0){
            float mean = a * (1.0f / DMODEL);
            float var  = q * (1.0f / DMODEL) - mean * mean;
            stat[0] = mean; stat[1] = rsqrtf(var + 1e-5f);
        }
    }
    __syncthreads();
    float mean = stat[0], rstd = stat[1];
    float4 g  = ((const float4*)gamma)[tid];
    float4 be = ((const float4*)beta)[tid];
    float4 y;
    y.x = tf32r((v.x - mean) * rstd * g.x + be.x);
    y.y = tf32r((v.y - mean) * rstd * g.y + be.y);
    y.z = tf32r((v.z - mean) * rstd * g.z + be.z);
    y.w = tf32r((v.w - mean) * rstd * g.w + be.w);
    ((float4*)(g_xn + (size_t)row * DMODEL))[tid] = y;
}

// ---------------- Kernel 2: QKV projection GEMM (LDSM + 3-stage cp.async) --
#define PA_LD 36
#define PB_LD 36
#define PROJ_STAGE_A (128*PA_LD)
#define PROJ_STAGE_B (128*PB_LD)
#define PROJ_SMEM_FLOATS (3*(PROJ_STAGE_A + PROJ_STAGE_B))
#define PROJ_SMEM_BYTES  (PROJ_SMEM_FLOATS*4)

__global__ void __launch_bounds__(256,2) proj_kernel(
    const float* __restrict__ bq, const float* __restrict__ bk,
    const float* __restrict__ bv)
{
    extern __shared__ float psm[];
    float* Asb = psm;
    float* Bsb = psm + 3*PROJ_STAGE_A;

    int m0 = blockIdx.x * 128;
    int by = blockIdx.y;
    int wsel = by >> 3;
    int n0 = (by & 7) * 128;
    const float* W    = g_wt + (size_t)wsel * DMODEL * DMODEL;   // [n][k]
    const float* bias = (wsel == 0) ? bq : (wsel == 1) ? bk : bv;
    float* out        = (wsel == 0) ? g_q : (wsel == 1) ? g_k : g_v;

    int tid = threadIdx.x, lane = tid & 31, wid = tid >> 5;
    int gid = lane >> 2, tig = lane & 3;
    int wr = wid >> 2, wc = wid & 3;
    int aRow = lane & 15,                aCol = (lane & 16) ? 4 : 0;
    int bRow = ((lane & 16) ? 8 : 0) | (lane & 7), bCol = (lane & 8) ? 4 : 0;

    unsigned As_u = (unsigned)__cvta_generic_to_shared(Asb);
    unsigned Bs_u = (unsigned)__cvta_generic_to_shared(Bsb);

    float acc[4][4][4];
    #pragma unroll
    for (int i=0;i<4;i++)
      #pragma unroll
      for (int j=0;j<4;j++)
        #pragma unroll
        for (int r=0;r<4;r++) acc[i][j][r] = 0.f;

    auto load_stage = [&](int st, int k0){
        float* As = Asb + st*PROJ_STAGE_A;
        float* Bs = Bsb + st*PROJ_STAGE_B;
        #pragma unroll
        for (int s = 0; s < 4; s++){
            int idx = tid + 256*s;
            int r = idx >> 3, c4 = idx & 7;
            cpa16(&As[r*PA_LD + c4*4],
                  g_xn + (size_t)(m0 + r)*1024 + k0 + c4*4);
            cpa16(&Bs[r*PB_LD + c4*4],
                  W + (size_t)(n0 + r)*1024 + k0 + c4*4);
        }
    };

    load_stage(0, 0);  cp_commit();
    load_stage(1, 32); cp_commit();

    for (int it = 0; it < 32; it++){
        if (it < 31) cp_wait1(); else cp_wait0();
        __syncthreads();
        if (it + 2 < 32){ load_stage((it+2)%3, (it+2)*32); cp_commit(); }
        unsigned Asu = As_u + (unsigned)((it%3)*PROJ_STAGE_A*4);
        unsigned Bsu = Bs_u + (unsigned)((it%3)*PROJ_STAGE_B*4);
        #pragma unroll
        for (int ks = 0; ks < 32; ks += 8){
            unsigned afr[4][4], bfr[2][4];
            #pragma unroll
            for (int i=0;i<4;i++)
                ldsm4(afr[i], Asu + (((wr*64+i*16+aRow)*PA_LD + ks + aCol)<<2));
            #pragma unroll
            for (int jj=0;jj<2;jj++)
                ldsm4(bfr[jj], Bsu + (((wc*32+jj*16+bRow)*PB_LD + ks + bCol)<<2));
            #pragma unroll
            for (int i=0;i<4;i++)
                #pragma unroll
                for (int j=0;j<4;j++)
                    MMA_TF32(acc[i][j], afr[i], &bfr[j>>1][(j&1)*2]);
        }
    }
    #pragma unroll
    for (int i=0;i<4;i++){
        int m  = m0 + wr*64 + i*16 + gid;
        int bb = m >> 10, s1 = m & 1023;
        #pragma unroll
        for (int j=0;j<4;j++){
            int nl = n0 + wc*32 + j*8 + 2*tig;
            int h = nl >> 6, d = nl & 63;
            float c0 = tf32r(acc[i][j][0] + bias[nl]);
            float c1 = tf32r(acc[i][j][1] + bias[nl+1]);
            float c2 = tf32r(acc[i][j][2] + bias[nl]);
            float c3 = tf32r(acc[i][j][3] + bias[nl+1]);
            if (wsel < 2){
                size_t base = ((size_t)(bb*NH + h)*SEQ + s1)*HD + d;
                *(float2*)(out + base) = make_float2(c0, c1);
                *(float2*)(out + base + (size_t)8*HD) = make_float2(c2, c3);
            } else {
                size_t base = ((size_t)(bb*NH + h)*HD + d)*SEQ + s1;
                out[base]            = c0;
                out[base + SEQ]      = c1;
                out[base + 8]        = c2;
                out[base + SEQ + 8]  = c3;
            }
        }
    }
}

// ---------------- Kernel 3: attention, Q64/K64 tiles, 3 CTAs/SM -------------
#define TLD 68
#define ATTN_SMEM_FLOATS (4*64*TLD + 128)
#define ATTN_SMEM_BYTES  (ATTN_SMEM_FLOATS*4)

__global__ void __launch_bounds__(256,3) attn_kernel(
    const float* __restrict__ x, const int* __restrict__ kvlen,
    float* __restrict__ seq, float* __restrict__ attn_out)
{
    extern __shared__ float sm[];
    float* Qs   = sm;                  // 64 q-rows x 64 d
    float* Ks   = Qs + 64*TLD;         // 64 keys  x 64 d
    float* Vt   = Ks + 64*TLD;         // 64 d     x 64 keys
    float* Ps   = Vt + 64*TLD;         // 64 q     x 64 keys
    float* rsum = Ps + 64*TLD;
    float* rinv = rsum + 64;

    int bh = blockIdx.x;
    int qt = 15 - blockIdx.y;                 // heavy tiles first
    int b = bh >> 4, h = bh & 15;
    int len = kvlen[b];
    int tid = threadIdx.x, lane = tid & 31, wid = tid >> 5;
    int gid = lane >> 2, tig = lane & 3;
    int wr = wid >> 2, wc = wid & 3;          // 8 warps as 2x4
    int q_base = qt * 64;
    int aRow = lane & 15,                aCol = (lane & 16) ? 4 : 0;
    int bRow = ((lane & 16) ? 8 : 0) | (lane & 7), bCol = (lane & 8) ? 4 : 0;

    unsigned Qs_u = (unsigned)__cvta_generic_to_shared(Qs);
    unsigned Ks_u = (unsigned)__cvta_generic_to_shared(Ks);
    unsigned Vt_u = (unsigned)__cvta_generic_to_shared(Vt);
    unsigned Ps_u = (unsigned)__cvta_generic_to_shared(Ps);

    const float* qp    = g_q + ((size_t)bh << 16) + (size_t)q_base * 64;
    const float* kbase = g_k + ((size_t)bh << 16);
    const float* vbase = g_v + ((size_t)bh << 16);   // (64, SEQ) transposed
    float* attn_base   = attn_out + ((size_t)bh << 20) + (size_t)q_base * 1024;

    // load Q tile
    #pragma unroll
    for (int s = 0; s < 4; s++){
        int idx = tid + 256*s;
        int r = idx >> 4, c4 = idx & 15;
        cpa16(&Qs[r*TLD + c4*4], qp + (size_t)idx*4);
    }
    cp_commit();

    // zero-fill fully-masked causal tiles (overlaps Q load)
    for (int kt = qt + 1; kt < 16; kt++){
        float* aout = attn_base + kt*64;
        #pragma unroll
        for (int s = 0; s < 4; s++){
            int idx = tid + 256*s;
            int r = idx >> 4, c4 = idx & 15;
            *(float4*)(aout + (size_t)r*1024 + c4*4) = make_float4(0.f,0.f,0.f,0.f);
        }
    }
    if (tid < 64) rsum[tid] = 0.f;

    float oacc[2][2][4];
    #pragma unroll
    for (int i=0;i<2;i++)
      #pragma unroll
      for (int j=0;j<2;j++)
        #pragma unroll
        for (int r=0;r<4;r++) oacc[i][j][r] = 0.f;
    float part[4] = {0.f, 0.f, 0.f, 0.f};

    for (int kt = 0; kt <= qt; kt++){
        __syncthreads();   // prev iter's Ps/Ks/Vt consumers done; Q ready after wait below
        // issue K(kt), V(kt)
        {
            const float* kp = kbase + (size_t)kt * 4096;
            const float* vp = vbase + (size_t)kt * 64;
            #pragma unroll
            for (int s = 0; s < 4; s++){
                int idx = tid + 256*s;
                int r = idx >> 4, c4 = idx & 15;
                cpa16(&Ks[r*TLD + c4*4], kp + (size_t)idx*4);
                cpa16(&Vt[r*TLD + c4*4], vp + (size_t)r*SEQ + c4*4);
            }
            cp_commit();
        }
        // overlap: write unnormalized tile kt-1 (Ps still valid)
        if (kt > 0){
            float* aout = attn_base + (kt-1)*64;
            #pragma unroll
            for (int s = 0; s < 4; s++){
                int idx = tid + 256*s;
                int r = idx >> 4, c4 = idx & 15;
                float4 v = *(float4*)(&Ps[r*TLD + c4*4]);
                *(float4*)(aout + (size_t)r*1024 + c4*4) = v;
            }
        }
        cp_wait0();
        __syncthreads();

        // ---- scores 64x64 : warp tile 32x16 (LDSM) ----
        float sacc[2][2][4];
        #pragma unroll
        for (int i=0;i<2;i++)
          #pragma unroll
          for (int j=0;j<2;j++)
            #pragma unroll
            for (int r=0;r<4;r++) sacc[i][j][r] = 0.f;
        #pragma unroll
        for (int kst = 0; kst < 8; kst++){
            unsigned afr[2][4], bfr[4];
            #pragma unroll
            for (int i=0;i<2;i++)
                ldsm4(afr[i], Qs_u + (((wr*32+i*16+aRow)*TLD + kst*8 + aCol)<<2));
            ldsm4(bfr, Ks_u + (((wc*16+bRow)*TLD + kst*8 + bCol)<<2));
            #pragma unroll
            for (int i=0;i<2;i++){
                MMA_TF32(sacc[i][0], afr[i], &bfr[0]);
                MMA_TF32(sacc[i][1], afr[i], &bfr[2]);
            }
        }

        // ---- masked unnormalized exp -> Ps (tf32), rowsums ----
        #pragma unroll
        for (int i=0;i<2;i++){
            int r0  = wr*32 + i*16 + gid;
            int qr0 = q_base + r0, qr1 = qr0 + 8;
            #pragma unroll
            for (int j=0;j<2;j++){
                int cl = wc*16 + j*8 + 2*tig;
                int c0 = kt*64 + cl, c1 = c0 + 1;
                float p00 = (c0 <= qr0 && c0 < len) ? __expf(sacc[i][j][0]*0.125f) : 0.f;
                float p01 = (c1 <= qr0 && c1 < len) ? __expf(sacc[i][j][1]*0.125f) : 0.f;
                float p10 = (c0 <= qr1 && c0 < len) ? __expf(sacc[i][j][2]*0.125f) : 0.f;
                float p11 = (c1 <= qr1 && c1 < len) ? __expf(sacc[i][j][3]*0.125f) : 0.f;
                Ps[r0*TLD + cl]       = tf32r(p00);
                Ps[r0*TLD + cl + 1]   = tf32r(p01);
                Ps[(r0+8)*TLD + cl]   = tf32r(p10);
                Ps[(r0+8)*TLD + cl+1] = tf32r(p11);
                part[i*2+0] += p00 + p01;
                part[i*2+1] += p10 + p11;
            }
        }
        __syncthreads();   // Ps visible

        // ---- O += P @ V : warp tile 32x16 (LDSM) ----
        #pragma unroll
        for (int ks = 0; ks < 64; ks += 8){
            unsigned afr[2][4], bfr[4];
            #pragma unroll
            for (int i=0;i<2;i++)
                ldsm4(afr[i], Ps_u + (((wr*32+i*16+aRow)*TLD + ks + aCol)<<2));
            ldsm4(bfr, Vt_u + (((wc*16+bRow)*TLD + ks + bCol)<<2));
            #pragma unroll
            for (int i=0;i<2;i++){
                MMA_TF32(oacc[i][0], afr[i], &bfr[0]);
                MMA_TF32(oacc[i][1], afr[i], &bfr[2]);
            }
        }
    }

    // reduce rowsums
    #pragma unroll
    for (int pi = 0; pi < 4; pi++){
        float p = part[pi];
        p += __shfl_xor_sync(0xffffffffu, p, 1);
        p += __shfl_xor_sync(0xffffffffu, p, 2);
        if (tig == 0){
            int r = wr*32 + (pi >> 1)*16 + gid + (pi & 1)*8;
            atomicAdd(&rsum[r], p);
        }
    }
    __syncthreads();
    if (tid < 64){
        float iv = 1.0f / rsum[tid];
        rinv[tid] = iv;
        g_rinv[bh*SEQ + q_base + tid] = iv;
    }
    __syncthreads();

    // tail: write diagonal tile normalized, directly from Ps
    {
        float* aout = attn_base + qt*64;
        #pragma unroll
        for (int s = 0; s < 4; s++){
            int idx = tid + 256*s;
            int r = idx >> 4, c4 = idx & 15;
            float inv = rinv[r];
            float4 v = *(float4*)(&Ps[r*TLD + c4*4]);
            v.x *= inv; v.y *= inv; v.z *= inv; v.w *= inv;
            *(float4*)(aout + (size_t)r*1024 + c4*4) = v;
        }
    }

    // epilogue: seq = x + O * rinv
    #pragma unroll
    for (int i=0;i<2;i++){
        int r0 = wr*32 + i*16 + gid;
        int q0 = q_base + r0;
        float inv0 = rinv[r0], inv1 = rinv[r0 + 8];
        #pragma unroll
        for (int j=0;j<2;j++){
            int col = wc*16 + j*8 + 2*tig;
            size_t a0 = ((size_t)(b*SEQ + q0))*DMODEL + h*HD + col;
            float2 xa = *(const float2*)(x + a0);
            *(float2*)(seq + a0) = make_float2(xa.x + oacc[i][j][0]*inv0,
                                               xa.y + oacc[i][j][1]*inv0);
            size_t a1 = a0 + (size_t)8*DMODEL;
            float2 xb = *(const float2*)(x + a1);
            *(float2*)(seq + a1) = make_float2(xb.x + oacc[i][j][2]*inv1,
                                               xb.y + oacc[i][j][3]*inv1);
        }
    }
}

// ---------------- Kernel 4: rescale strictly-below-diagonal tiles -----------
__global__ void __launch_bounds__(256) norm_kernel(float* __restrict__ attn)
{
    int bid = blockIdx.x;                 // 64 bh * 120 (qt,kt) pairs, kt<qt
    int bh = bid & 63;
    int t  = bid >> 6;                    // 0..119
    int qt = 1;
    #pragma unroll
    for (int q = 15; q >= 2; q--) if (t >= (q*(q-1))/2){ qt = q; break; }
    int kt = t - (qt*(qt-1))/2;

    int tid = threadIdx.x;
    float* base = attn + ((size_t)bh << 20) + ((size_t)qt*64*1024) + kt*64;
    const float* rv = g_rinv + bh*SEQ + qt*64;
    #pragma unroll
    for (int s = 0; s < 4; s++){
        int idx = tid + 256*s;
        int r = idx >> 4, c4 = idx & 15;
        float inv = rv[r];
        float* p = base + (size_t)r*1024 + c4*4;
        float4 v = *(float4*)p;
        v.x *= inv; v.y *= inv; v.z *= inv; v.w *= inv;
        *(float4*)p = v;
    }
}

// ---------------- launch ----------------------------------------------------
extern "C" void kernel_launch(void* const* d_in, const int* in_sizes, int n_in,
                              void* d_out, int out_size)
{
    const float* x     = (const float*)d_in[0];
    const int*   kvlen = (const int*)  d_in[3];
    const float* gamma = (const float*)d_in[4];
    const float* beta  = (const float*)d_in[5];
    const float* Wq    = (const float*)d_in[6];
    const float* bq    = (const float*)d_in[7];
    const float* Wk    = (const float*)d_in[8];
    const float* bk    = (const float*)d_in[9];
    const float* Wv    = (const float*)d_in[10];
    const float* bv    = (const float*)d_in[11];

    float* seq  = (float*)d_out;
    float* attn = seq + (size_t)BATCH*SEQ*DMODEL;

    cudaFuncSetAttribute(proj_kernel,
        cudaFuncAttributeMaxDynamicSharedMemorySize, PROJ_SMEM_BYTES);
    cudaFuncSetAttribute(attn_kernel,
        cudaFuncAttributeMaxDynamicSharedMemorySize, ATTN_SMEM_BYTES);

    prep_w<<<dim3(16,16,3), 256>>>(Wq, Wk, Wv);
    ln_kernel<<<BATCH*SEQ, 256>>>(x, gamma, beta);
    proj_kernel<<<dim3(32, 24), 256, PROJ_SMEM_BYTES>>>(bq, bk, bv);
    attn_kernel<<<dim3(64, 16), 256, ATTN_SMEM_BYTES>>>(x, kvlen, seq, attn);
    norm_kernel<<<64*120, 256>>>(attn);
}

// round 10
// speedup vs baseline: 1.4446x; 1.0205x over previous
#include <cuda_runtime.h>
#include <cstdint>
#include <cstddef>

#define BATCH 4
#define SEQ   1024
#define DMODEL 1024
#define NH    16
#define HD    64

// ---------------- scratch (device globals: no runtime allocation) ----------
__device__ float g_xn[BATCH*SEQ*DMODEL];     // layernormed input, tf32-rounded
__device__ float g_wt[3*DMODEL*DMODEL];      // W^T per slice: [n][k], tf32-rounded
__device__ float g_q[BATCH*SEQ*DMODEL];      // (B,H,S,64), tf32-rounded
__device__ float g_k[BATCH*SEQ*DMODEL];      // (B,H,S,64), tf32-rounded
__device__ float g_v[BATCH*SEQ*DMODEL];      // TRANSPOSED: (B,H,64,S), tf32-rounded
__device__ float g_rinv[BATCH*NH*SEQ];       // 1/rowsum per (b,h,q)

__device__ __forceinline__ float tf32r(float f){
    unsigned u; asm("cvt.rna.tf32.f32 %0, %1;" : "=r"(u) : "f"(f));
    return __uint_as_float(u);
}

__device__ __forceinline__ void cpa16(void* dst, const void* src){
    unsigned d = (unsigned)__cvta_generic_to_shared(dst);
    asm volatile("cp.async.cg.shared.global [%0], [%1], 16;" :: "r"(d), "l"(src));
}
__device__ __forceinline__ void cp_commit(){ asm volatile("cp.async.commit_group;"); }
__device__ __forceinline__ void cp_wait0(){ asm volatile("cp.async.wait_group 0;"); }
__device__ __forceinline__ void cp_wait1(){ asm volatile("cp.async.wait_group 1;"); }

__device__ __forceinline__ void ldsm4(unsigned* r, unsigned addr){
    asm volatile("ldmatrix.sync.aligned.m8n8.x4.shared.b16 {%0,%1,%2,%3}, [%4];"
        : "=r"(r[0]),"=r"(r[1]),"=r"(r[2]),"=r"(r[3]) : "r"(addr));
}

#define MMA_TF32(d, a, b_) \
  asm volatile("mma.sync.aligned.m16n8k8.row.col.f32.tf32.tf32.f32 " \
    "{%0,%1,%2,%3},{%4,%5,%6,%7},{%8,%9},{%0,%1,%2,%3};" \
    : "+f"((d)[0]),"+f"((d)[1]),"+f"((d)[2]),"+f"((d)[3]) \
    : "r"((a)[0]),"r"((a)[1]),"r"((a)[2]),"r"((a)[3]),"r"((b_)[0]),"r"((b_)[1]))

// ---------------- Kernel 0: round W to tf32 AND transpose -> [n][k] --------
__global__ void __launch_bounds__(256) prep_w(const float* __restrict__ Wq,
    const float* __restrict__ Wk, const float* __restrict__ Wv)
{
    __shared__ float t[64][65];
    int w = blockIdx.z;
    const float* W = (w == 0) ? Wq : (w == 1) ? Wk : Wv;
    float* out = g_wt + (size_t)w * DMODEL * DMODEL;
    int kb = blockIdx.y * 64, nb = blockIdx.x * 64;
    int tid = threadIdx.x;
    #pragma unroll
    for (int i = 0; i < 4; i++){
        int idx = tid + 256*i;
        int r = idx >> 4, c4 = idx & 15;
        float4 v = *(const float4*)(W + (size_t)(kb + r)*1024 + nb + c4*4);
        t[r][c4*4+0] = tf32r(v.x); t[r][c4*4+1] = tf32r(v.y);
        t[r][c4*4+2] = tf32r(v.z); t[r][c4*4+3] = tf32r(v.w);
    }
    __syncthreads();
    #pragma unroll
    for (int i = 0; i < 4; i++){
        int idx = tid + 256*i;
        int n = idx >> 4, k4 = idx & 15;
        float4 v = make_float4(t[k4*4+0][n], t[k4*4+1][n], t[k4*4+2][n], t[k4*4+3][n]);
        *(float4*)(out + (size_t)(nb + n)*1024 + kb + k4*4) = v;
    }
}

// ---------------- Kernel 1: LayerNorm (fp32 stats, tf32-rounded output) ----
__global__ void __launch_bounds__(256) ln_kernel(const float* __restrict__ x,
    const float* __restrict__ gamma, const float* __restrict__ beta)
{
    int row = blockIdx.x;
    int tid = threadIdx.x, lane = tid & 31, wid = tid >> 5;
    const float4* xr = (const float4*)(x + (size_t)row * DMODEL);
    float4 v = xr[tid];
    float s  = v.x + v.y + v.z + v.w;
    float sq = v.x*v.x + v.y*v.y + v.z*v.z + v.w*v.w;
    #pragma unroll
    for (int o = 16; o > 0; o >>= 1){
        s  += __shfl_xor_sync(0xffffffffu, s,  o);
        sq += __shfl_xor_sync(0xffffffffu, sq, o);
    }
    __shared__ float ws[8], wq[8], stat[2];
    if (lane == 0){ ws[wid] = s; wq[wid] = sq; }
    __syncthreads();
    if (wid == 0){
        float a = (lane < 8) ? ws[lane] : 0.f;
        float q = (lane < 8) ? wq[lane] : 0.f;
        #pragma unroll
        for (int o = 4; o > 0; o >>= 1){
            a += __shfl_xor_sync(0xffffffffu, a, o);
            q += __shfl_xor_sync(0xffffffffu, q, o);
        }
        if (lane == 0){
            float mean = a * (1.0f / DMODEL);
            float var  = q * (1.0f / DMODEL) - mean * mean;
            stat[0] = mean; stat[1] = rsqrtf(var + 1e-5f);
        }
    }
    __syncthreads();
    float mean = stat[0], rstd = stat[1];
    float4 g  = ((const float4*)gamma)[tid];
    float4 be = ((const float4*)beta)[tid];
    float4 y;
    y.x = tf32r((v.x - mean) * rstd * g.x + be.x);
    y.y = tf32r((v.y - mean) * rstd * g.y + be.y);
    y.z = tf32r((v.z - mean) * rstd * g.z + be.z);
    y.w = tf32r((v.w - mean) * rstd * g.w + be.w);
    ((float4*)(g_xn + (size_t)row * DMODEL))[tid] = y;
}

// ---------------- Kernel 2: QKV projection GEMM (LDSM + 3-stage cp.async) --
#define PA_LD 36
#define PB_LD 36
#define PROJ_STAGE_A (128*PA_LD)
#define PROJ_STAGE_B (128*PB_LD)
#define PROJ_SMEM_FLOATS (3*(PROJ_STAGE_A + PROJ_STAGE_B))
#define PROJ_SMEM_BYTES  (PROJ_SMEM_FLOATS*4)

__global__ void __launch_bounds__(256,2) proj_kernel(
    const float* __restrict__ bq, const float* __restrict__ bk,
    const float* __restrict__ bv)
{
    extern __shared__ float psm[];
    float* Asb = psm;
    float* Bsb = psm + 3*PROJ_STAGE_A;

    int m0 = blockIdx.x * 128;
    int by = blockIdx.y;
    int wsel = by >> 3;
    int n0 = (by & 7) * 128;
    const float* W    = g_wt + (size_t)wsel * DMODEL * DMODEL;   // [n][k]
    const float* bias = (wsel == 0) ? bq : (wsel == 1) ? bk : bv;
    float* out        = (wsel == 0) ? g_q : (wsel == 1) ? g_k : g_v;

    int tid = threadIdx.x, lane = tid & 31, wid = tid >> 5;
    int gid = lane >> 2, tig = lane & 3;
    int wr = wid >> 2, wc = wid & 3;
    int aRow = lane & 15,                aCol = (lane & 16) ? 4 : 0;
    int bRow = ((lane & 16) ? 8 : 0) | (lane & 7), bCol = (lane & 8) ? 4 : 0;

    unsigned As_u = (unsigned)__cvta_generic_to_shared(Asb);
    unsigned Bs_u = (unsigned)__cvta_generic_to_shared(Bsb);

    float acc[4][4][4];
    #pragma unroll
    for (int i=0;i<4;i++)
      #pragma unroll
      for (int j=0;j<4;j++)
        #pragma unroll
        for (int r=0;r<4;r++) acc[i][j][r] = 0.f;

    auto load_stage = [&](int st, int k0){
        float* As = Asb + st*PROJ_STAGE_A;
        float* Bs = Bsb + st*PROJ_STAGE_B;
        #pragma unroll
        for (int s = 0; s < 4; s++){
            int idx = tid + 256*s;
            int r = idx >> 3, c4 = idx & 7;
            cpa16(&As[r*PA_LD + c4*4],
                  g_xn + (size_t)(m0 + r)*1024 + k0 + c4*4);
            cpa16(&Bs[r*PB_LD + c4*4],
                  W + (size_t)(n0 + r)*1024 + k0 + c4*4);
        }
    };

    load_stage(0, 0);  cp_commit();
    load_stage(1, 32); cp_commit();

    for (int it = 0; it < 32; it++){
        if (it < 31) cp_wait1(); else cp_wait0();
        __syncthreads();
        if (it + 2 < 32){ load_stage((it+2)%3, (it+2)*32); cp_commit(); }
        unsigned Asu = As_u + (unsigned)((it%3)*PROJ_STAGE_A*4);
        unsigned Bsu = Bs_u + (unsigned)((it%3)*PROJ_STAGE_B*4);
        #pragma unroll
        for (int ks = 0; ks < 32; ks += 8){
            unsigned afr[4][4], bfr[2][4];
            #pragma unroll
            for (int i=0;i<4;i++)
                ldsm4(afr[i], Asu + (((wr*64+i*16+aRow)*PA_LD + ks + aCol)<<2));
            #pragma unroll
            for (int jj=0;jj<2;jj++)
                ldsm4(bfr[jj], Bsu + (((wc*32+jj*16+bRow)*PB_LD + ks + bCol)<<2));
            #pragma unroll
            for (int i=0;i<4;i++)
                #pragma unroll
                for (int j=0;j<4;j++)
                    MMA_TF32(acc[i][j], afr[i], &bfr[j>>1][(j&1)*2]);
        }
    }
    #pragma unroll
    for (int i=0;i<4;i++){
        int m  = m0 + wr*64 + i*16 + gid;
        int bb = m >> 10, s1 = m & 1023;
        #pragma unroll
        for (int j=0;j<4;j++){
            int nl = n0 + wc*32 + j*8 + 2*tig;
            int h = nl >> 6, d = nl & 63;
            float c0 = tf32r(acc[i][j][0] + bias[nl]);
            float c1 = tf32r(acc[i][j][1] + bias[nl+1]);
            float c2 = tf32r(acc[i][j][2] + bias[nl]);
            float c3 = tf32r(acc[i][j][3] + bias[nl+1]);
            if (wsel < 2){
                size_t base = ((size_t)(bb*NH + h)*SEQ + s1)*HD + d;
                *(float2*)(out + base) = make_float2(c0, c1);
                *(float2*)(out + base + (size_t)8*HD) = make_float2(c2, c3);
            } else {
                size_t base = ((size_t)(bb*NH + h)*HD + d)*SEQ + s1;
                out[base]            = c0;
                out[base + SEQ]      = c1;
                out[base + 8]        = c2;
                out[base + SEQ + 8]  = c3;
            }
        }
    }
}

// ---------------- Kernel 3: rowsum pre-pass (QK^T + exp, no stores) --------
#define TLD 68
#define RS_SMEM_FLOATS (3*64*TLD + 128)
#define RS_SMEM_BYTES  (RS_SMEM_FLOATS*4)

__global__ void __launch_bounds__(256,4) rowsum_kernel(const int* __restrict__ kvlen)
{
    extern __shared__ float sm[];
    float* Qs   = sm;
    float* Ks0  = Qs  + 64*TLD;
    float* Ks1  = Ks0 + 64*TLD;
    float* rsum = Ks1 + 64*TLD;
    float* Kbuf[2] = {Ks0, Ks1};

    int bh = blockIdx.x;
    int qt = 15 - blockIdx.y;
    int b = bh >> 4;
    int len = kvlen[b];
    int tid = threadIdx.x, lane = tid & 31, wid = tid >> 5;
    int gid = lane >> 2, tig = lane & 3;
    int wr = wid >> 2, wc = wid & 3;          // 8 warps as 2x4
    int q_base = qt * 64;
    int aRow = lane & 15,                aCol = (lane & 16) ? 4 : 0;
    int bRow = ((lane & 16) ? 8 : 0) | (lane & 7), bCol = (lane & 8) ? 4 : 0;

    unsigned Qs_u = (unsigned)__cvta_generic_to_shared(Qs);
    unsigned Ks_u[2] = {(unsigned)__cvta_generic_to_shared(Ks0),
                        (unsigned)__cvta_generic_to_shared(Ks1)};

    const float* qp    = g_q + ((size_t)bh << 16) + (size_t)q_base * 64;
    const float* kbase = g_k + ((size_t)bh << 16);

    // group 0: Q + K(0)
    #pragma unroll
    for (int s = 0; s < 4; s++){
        int idx = tid + 256*s;
        int r = idx >> 4, c4 = idx & 15;
        cpa16(&Qs[r*TLD + c4*4], qp + (size_t)idx*4);
        cpa16(&Ks0[r*TLD + c4*4], kbase + (size_t)idx*4);
    }
    cp_commit();
    if (tid < 64) rsum[tid] = 0.f;

    float part[4] = {0.f, 0.f, 0.f, 0.f};

    for (int kt = 0; kt <= qt; kt++){
        int buf = kt & 1;
        __syncthreads();                    // Kbuf[buf^1] readers from prev iter done
        if (kt < qt){
            const float* kp = kbase + (size_t)(kt+1) * 4096;
            #pragma unroll
            for (int s = 0; s < 4; s++){
                int idx = tid + 256*s;
                int r = idx >> 4, c4 = idx & 15;
                cpa16(&Kbuf[buf^1][r*TLD + c4*4], kp + (size_t)idx*4);
            }
            cp_commit();
            cp_wait1();
        } else cp_wait0();
        __syncthreads();

        float sacc[2][2][4];
        #pragma unroll
        for (int i=0;i<2;i++)
          #pragma unroll
          for (int j=0;j<2;j++)
            #pragma unroll
            for (int r=0;r<4;r++) sacc[i][j][r] = 0.f;
        unsigned Kbu = Ks_u[buf];
        #pragma unroll
        for (int kst = 0; kst < 8; kst++){
            unsigned afr[2][4], bfr[4];
            #pragma unroll
            for (int i=0;i<2;i++)
                ldsm4(afr[i], Qs_u + (((wr*32+i*16+aRow)*TLD + kst*8 + aCol)<<2));
            ldsm4(bfr, Kbu + (((wc*16+bRow)*TLD + kst*8 + bCol)<<2));
            #pragma unroll
            for (int i=0;i<2;i++){
                MMA_TF32(sacc[i][0], afr[i], &bfr[0]);
                MMA_TF32(sacc[i][1], afr[i], &bfr[2]);
            }
        }
        #pragma unroll
        for (int i=0;i<2;i++){
            int r0  = wr*32 + i*16 + gid;
            int qr0 = q_base + r0, qr1 = qr0 + 8;
            #pragma unroll
            for (int j=0;j<2;j++){
                int cl = wc*16 + j*8 + 2*tig;
                int c0 = kt*64 + cl, c1 = c0 + 1;
                float p00 = (c0 <= qr0 && c0 < len) ? __expf(sacc[i][j][0]*0.125f) : 0.f;
                float p01 = (c1 <= qr0 && c1 < len) ? __expf(sacc[i][j][1]*0.125f) : 0.f;
                float p10 = (c0 <= qr1 && c0 < len) ? __expf(sacc[i][j][2]*0.125f) : 0.f;
                float p11 = (c1 <= qr1 && c1 < len) ? __expf(sacc[i][j][3]*0.125f) : 0.f;
                part[i*2+0] += p00 + p01;
                part[i*2+1] += p10 + p11;
            }
        }
    }

    #pragma unroll
    for (int pi = 0; pi < 4; pi++){
        float p = part[pi];
        p += __shfl_xor_sync(0xffffffffu, p, 1);
        p += __shfl_xor_sync(0xffffffffu, p, 2);
        if (tig == 0){
            int r = wr*32 + (pi >> 1)*16 + gid + (pi & 1)*8;
            atomicAdd(&rsum[r], p);
        }
    }
    __syncthreads();
    if (tid < 64)
        g_rinv[bh*SEQ + q_base + tid] = 1.0f / rsum[tid];
}

// ---------------- Kernel 4: attention (writes normalized tiles) ------------
#define ATTN_SMEM_FLOATS (4*64*TLD + 128)
#define ATTN_SMEM_BYTES  (ATTN_SMEM_FLOATS*4)

__global__ void __launch_bounds__(256,3) attn_kernel(
    const float* __restrict__ x, const int* __restrict__ kvlen,
    float* __restrict__ seq, float* __restrict__ attn_out)
{
    extern __shared__ float sm[];
    float* Qs   = sm;
    float* Ks   = Qs + 64*TLD;
    float* Vt   = Ks + 64*TLD;
    float* Ps   = Vt + 64*TLD;
    float* rinv = Ps + 64*TLD;

    int bh = blockIdx.x;
    int qt = 15 - blockIdx.y;
    int b = bh >> 4, h = bh & 15;
    int len = kvlen[b];
    int tid = threadIdx.x, lane = tid & 31, wid = tid >> 5;
    int gid = lane >> 2, tig = lane & 3;
    int wr = wid >> 2, wc = wid & 3;
    int q_base = qt * 64;
    int aRow = lane & 15,                aCol = (lane & 16) ? 4 : 0;
    int bRow = ((lane & 16) ? 8 : 0) | (lane & 7), bCol = (lane & 8) ? 4 : 0;

    unsigned Qs_u = (unsigned)__cvta_generic_to_shared(Qs);
    unsigned Ks_u = (unsigned)__cvta_generic_to_shared(Ks);
    unsigned Vt_u = (unsigned)__cvta_generic_to_shared(Vt);
    unsigned Ps_u = (unsigned)__cvta_generic_to_shared(Ps);

    const float* qp    = g_q + ((size_t)bh << 16) + (size_t)q_base * 64;
    const float* kbase = g_k + ((size_t)bh << 16);
    const float* vbase = g_v + ((size_t)bh << 16);
    float* attn_base   = attn_out + ((size_t)bh << 20) + (size_t)q_base * 1024;

    #pragma unroll
    for (int s = 0; s < 4; s++){
        int idx = tid + 256*s;
        int r = idx >> 4, c4 = idx & 15;
        cpa16(&Qs[r*TLD + c4*4], qp + (size_t)idx*4);
    }
    cp_commit();

    if (tid < 64) rinv[tid] = g_rinv[bh*SEQ + q_base + tid];

    // zero-fill fully-masked causal tiles (overlaps Q load)
    for (int kt = qt + 1; kt < 16; kt++){
        float* aout = attn_base + kt*64;
        #pragma unroll
        for (int s = 0; s < 4; s++){
            int idx = tid + 256*s;
            int r = idx >> 4, c4 = idx & 15;
            *(float4*)(aout + (size_t)r*1024 + c4*4) = make_float4(0.f,0.f,0.f,0.f);
        }
    }

    float oacc[2][2][4];
    #pragma unroll
    for (int i=0;i<2;i++)
      #pragma unroll
      for (int j=0;j<2;j++)
        #pragma unroll
        for (int r=0;r<4;r++) oacc[i][j][r] = 0.f;

    for (int kt = 0; kt <= qt; kt++){
        __syncthreads();
        {
            const float* kp = kbase + (size_t)kt * 4096;
            const float* vp = vbase + (size_t)kt * 64;
            #pragma unroll
            for (int s = 0; s < 4; s++){
                int idx = tid + 256*s;
                int r = idx >> 4, c4 = idx & 15;
                cpa16(&Ks[r*TLD + c4*4], kp + (size_t)idx*4);
                cpa16(&Vt[r*TLD + c4*4], vp + (size_t)r*SEQ + c4*4);
            }
            cp_commit();
        }
        if (kt > 0){   // deferred store of previous (already normalized) tile
            float* aout = attn_base + (kt-1)*64;
            #pragma unroll
            for (int s = 0; s < 4; s++){
                int idx = tid + 256*s;
                int r = idx >> 4, c4 = idx & 15;
                float4 v = *(float4*)(&Ps[r*TLD + c4*4]);
                *(float4*)(aout + (size_t)r*1024 + c4*4) = v;
            }
        }
        cp_wait0();
        __syncthreads();

        float sacc[2][2][4];
        #pragma unroll
        for (int i=0;i<2;i++)
          #pragma unroll
          for (int j=0;j<2;j++)
            #pragma unroll
            for (int r=0;r<4;r++) sacc[i][j][r] = 0.f;
        #pragma unroll
        for (int kst = 0; kst < 8; kst++){
            unsigned afr[2][4], bfr[4];
            #pragma unroll
            for (int i=0;i<2;i++)
                ldsm4(afr[i], Qs_u + (((wr*32+i*16+aRow)*TLD + kst*8 + aCol)<<2));
            ldsm4(bfr, Ks_u + (((wc*16+bRow)*TLD + kst*8 + bCol)<<2));
            #pragma unroll
            for (int i=0;i<2;i++){
                MMA_TF32(sacc[i][0], afr[i], &bfr[0]);
                MMA_TF32(sacc[i][1], afr[i], &bfr[2]);
            }
        }

        // masked, NORMALIZED exp -> Ps (tf32-rounded)
        #pragma unroll
        for (int i=0;i<2;i++){
            int r0  = wr*32 + i*16 + gid;
            int qr0 = q_base + r0, qr1 = qr0 + 8;
            float inv0 = rinv[r0], inv1 = rinv[r0 + 8];
            #pragma unroll
            for (int j=0;j<2;j++){
                int cl = wc*16 + j*8 + 2*tig;
                int c0 = kt*64 + cl, c1 = c0 + 1;
                float p00 = (c0 <= qr0 && c0 < len) ? __expf(sacc[i][j][0]*0.125f)*inv0 : 0.f;
                float p01 = (c1 <= qr0 && c1 < len) ? __expf(sacc[i][j][1]*0.125f)*inv0 : 0.f;
                float p10 = (c0 <= qr1 && c0 < len) ? __expf(sacc[i][j][2]*0.125f)*inv1 : 0.f;
                float p11 = (c1 <= qr1 && c1 < len) ? __expf(sacc[i][j][3]*0.125f)*inv1 : 0.f;
                Ps[r0*TLD + cl]       = tf32r(p00);
                Ps[r0*TLD + cl + 1]   = tf32r(p01);
                Ps[(r0+8)*TLD + cl]   = tf32r(p10);
                Ps[(r0+8)*TLD + cl+1] = tf32r(p11);
            }
        }
        __syncthreads();

        #pragma unroll
        for (int ks = 0; ks < 64; ks += 8){
            unsigned afr[2][4], bfr[4];
            #pragma unroll
            for (int i=0;i<2;i++)
                ldsm4(afr[i], Ps_u + (((wr*32+i*16+aRow)*TLD + ks + aCol)<<2));
            ldsm4(bfr, Vt_u + (((wc*16+bRow)*TLD + ks + bCol)<<2));
            #pragma unroll
            for (int i=0;i<2;i++){
                MMA_TF32(oacc[i][0], afr[i], &bfr[0]);
                MMA_TF32(oacc[i][1], afr[i], &bfr[2]);
            }
        }
    }

    __syncthreads();
    // tail: store final (diagonal) tile
    {
        float* aout = attn_base + qt*64;
        #pragma unroll
        for (int s = 0; s < 4; s++){
            int idx = tid + 256*s;
            int r = idx >> 4, c4 = idx & 15;
            float4 v = *(float4*)(&Ps[r*TLD + c4*4]);
            *(float4*)(aout + (size_t)r*1024 + c4*4) = v;
        }
    }

    // epilogue: seq = x + O (O already normalized)
    #pragma unroll
    for (int i=0;i<2;i++){
        int r0 = wr*32 + i*16 + gid;
        int q0 = q_base + r0;
        #pragma unroll
        for (int j=0;j<2;j++){
            int col = wc*16 + j*8 + 2*tig;
            size_t a0 = ((size_t)(b*SEQ + q0))*DMODEL + h*HD + col;
            float2 xa = *(const float2*)(x + a0);
            *(float2*)(seq + a0) = make_float2(xa.x + oacc[i][j][0],
                                               xa.y + oacc[i][j][1]);
            size_t a1 = a0 + (size_t)8*DMODEL;
            float2 xb = *(const float2*)(x + a1);
            *(float2*)(seq + a1) = make_float2(xb.x + oacc[i][j][2],
                                               xb.y + oacc[i][j][3]);
        }
    }
}

// ---------------- launch ----------------------------------------------------
extern "C" void kernel_launch(void* const* d_in, const int* in_sizes, int n_in,
                              void* d_out, int out_size)
{
    const float* x     = (const float*)d_in[0];
    const int*   kvlen = (const int*)  d_in[3];
    const float* gamma = (const float*)d_in[4];
    const float* beta  = (const float*)d_in[5];
    const float* Wq    = (const float*)d_in[6];
    const float* bq    = (const float*)d_in[7];
    const float* Wk    = (const float*)d_in[8];
    const float* bk    = (const float*)d_in[9];
    const float* Wv    = (const float*)d_in[10];
    const float* bv    = (const float*)d_in[11];

    float* seq  = (float*)d_out;
    float* attn = seq + (size_t)BATCH*SEQ*DMODEL;

    cudaFuncSetAttribute(proj_kernel,
        cudaFuncAttributeMaxDynamicSharedMemorySize, PROJ_SMEM_BYTES);
    cudaFuncSetAttribute(rowsum_kernel,
        cudaFuncAttributeMaxDynamicSharedMemorySize, RS_SMEM_BYTES);
    cudaFuncSetAttribute(attn_kernel,
        cudaFuncAttributeMaxDynamicSharedMemorySize, ATTN_SMEM_BYTES);

    prep_w<<<dim3(16,16,3), 256>>>(Wq, Wk, Wv);
    ln_kernel<<<BATCH*SEQ, 256>>>(x, gamma, beta);
    proj_kernel<<<dim3(32, 24), 256, PROJ_SMEM_BYTES>>>(bq, bk, bv);
    rowsum_kernel<<<dim3(64, 16), 256, RS_SMEM_BYTES>>>(kvlen);
    attn_kernel<<<dim3(64, 16), 256, ATTN_SMEM_BYTES>>>(x, kvlen, seq, attn);
}